// round 1
// baseline (speedup 1.0000x reference)
#include <cuda_runtime.h>
#include <math.h>

#define BDIM   8
#define SEQ    1024
#define DMODEL 1024
#define NHEAD  16
#define DHEAD  64
#define SCALEF 0.125f
#define NEGV   (-1e9f)

// Scratch (device globals are the sanctioned scratch mechanism; no runtime alloc)
__device__ float g_qkv[(size_t)BDIM * SEQ * 3 * DMODEL];  // [B*N, 3D] ~100.7 MB
__device__ float g_ctx[(size_t)BDIM * SEQ * DMODEL];      // [B*N, D]  ~33.6 MB

// ---------------------------------------------------------------------------
// SGEMM: C[M,N] = A[M,K] @ B[K,N] (+ bias[N]); M,N multiples of 128, K of 8.
// 128x128 block tile, BK=8, 256 threads, 8x8 per thread.
// ---------------------------------------------------------------------------
__global__ __launch_bounds__(256)
void sgemm_kernel(const float* __restrict__ A, const float* __restrict__ B,
                  float* __restrict__ C, const float* __restrict__ bias,
                  int M, int N, int K)
{
    __shared__ float As[8][132];   // transposed A tile [k][m], padded
    __shared__ float Bs[8][128];   // B tile [k][n]

    const int tid = threadIdx.x;
    const int bm  = blockIdx.y * 128;
    const int bn  = blockIdx.x * 128;
    const int tx  = tid & 15;
    const int ty  = tid >> 4;
    const int rm  = ty * 8;
    const int rn  = tx * 8;

    const int arow = tid >> 1;          // 0..127
    const int acol = (tid & 1) * 4;     // 0 or 4
    const int brow = tid >> 5;          // 0..7
    const int bcol = (tid & 31) * 4;    // 0..124

    float acc[8][8];
#pragma unroll
    for (int i = 0; i < 8; i++)
#pragma unroll
        for (int j = 0; j < 8; j++) acc[i][j] = 0.f;

    for (int k0 = 0; k0 < K; k0 += 8) {
        float4 a4 = *(const float4*)(A + (size_t)(bm + arow) * K + k0 + acol);
        float4 b4 = *(const float4*)(B + (size_t)(k0 + brow) * N + bn + bcol);
        As[acol + 0][arow] = a4.x;
        As[acol + 1][arow] = a4.y;
        As[acol + 2][arow] = a4.z;
        As[acol + 3][arow] = a4.w;
        *(float4*)&Bs[brow][bcol] = b4;
        __syncthreads();

#pragma unroll
        for (int kk = 0; kk < 8; kk++) {
            float a[8], b[8];
            *(float4*)(a + 0) = *(const float4*)&As[kk][rm];
            *(float4*)(a + 4) = *(const float4*)&As[kk][rm + 4];
            *(float4*)(b + 0) = *(const float4*)&Bs[kk][rn];
            *(float4*)(b + 4) = *(const float4*)&Bs[kk][rn + 4];
#pragma unroll
            for (int i = 0; i < 8; i++)
#pragma unroll
                for (int j = 0; j < 8; j++) acc[i][j] += a[i] * b[j];
        }
        __syncthreads();
    }

    float bv[8];
#pragma unroll
    for (int j = 0; j < 8; j++) bv[j] = bias ? bias[bn + rn + j] : 0.f;

#pragma unroll
    for (int i = 0; i < 8; i++) {
        float* cp = C + (size_t)(bm + rm + i) * N + bn + rn;
        float4 v0, v1;
        v0.x = acc[i][0] + bv[0]; v0.y = acc[i][1] + bv[1];
        v0.z = acc[i][2] + bv[2]; v0.w = acc[i][3] + bv[3];
        v1.x = acc[i][4] + bv[4]; v1.y = acc[i][5] + bv[5];
        v1.z = acc[i][6] + bv[6]; v1.w = acc[i][7] + bv[7];
        *(float4*)(cp + 0) = v0;
        *(float4*)(cp + 4) = v1;
    }
}

// ---------------------------------------------------------------------------
// Attention: one block per (b, h, 64-query tile). 256 threads (16x16, 4x4 each)
// Phase 1: S = QK^T * scale with mask; raw S -> attn gmem; online rowmax/sumexp
// Phase 2: re-read S, p = exp(s-m)/l -> attn gmem; O = P @ V -> ctx
// ---------------------------------------------------------------------------
__global__ __launch_bounds__(256)
void attn_kernel(const float* __restrict__ qkv, const int* __restrict__ mask,
                 float* __restrict__ attn, float* __restrict__ ctx)
{
    __shared__ float T1[64][68];  // phase1: Qt[d][qrow]   phase2: Pt[k][qrow]
    __shared__ float T2[64][68];  // phase1: Kt[d][krow]   phase2: Vs[k][c]
    __shared__ float mrow[64];
    __shared__ float lrow[64];

    const int bh = blockIdx.y;            // b*NHEAD + h
    const int b  = bh / NHEAD;
    const int h  = bh % NHEAD;
    const int q0 = blockIdx.x * 64;
    const int tid = threadIdx.x;
    const int tx  = tid & 15;
    const int ty  = tid >> 4;
    const int rm  = ty * 4;               // query rows rm..rm+3
    const int cn  = tx * 4;               // key/dh cols cn..cn+3

    const int lr0 = tid >> 4;             // load row base (0..15)
    const int ld4 = (tid & 15) * 4;       // load col (0..60 step 4)

    // ---- load Q tile transposed: T1[d][qrow] ----
#pragma unroll
    for (int it = 0; it < 4; it++) {
        int row = lr0 + it * 16;
        float4 v = *(const float4*)(qkv + ((size_t)(b * SEQ + q0 + row)) * (3 * DMODEL)
                                    + h * DHEAD + ld4);
        T1[ld4 + 0][row] = v.x;
        T1[ld4 + 1][row] = v.y;
        T1[ld4 + 2][row] = v.z;
        T1[ld4 + 3][row] = v.w;
    }
    if (tid < 64) { mrow[tid] = -INFINITY; lrow[tid] = 0.f; }
    __syncthreads();

    float* attnbase = attn + ((size_t)bh * SEQ + q0) * SEQ;

    // ================= Phase 1 =================
    for (int kt = 0; kt < 16; kt++) {
        const int k0 = kt * 64;
        // load K tile transposed: T2[d][krow]
#pragma unroll
        for (int it = 0; it < 4; it++) {
            int kr = lr0 + it * 16;
            float4 v = *(const float4*)(qkv + ((size_t)(b * SEQ + k0 + kr)) * (3 * DMODEL)
                                        + DMODEL + h * DHEAD + ld4);
            T2[ld4 + 0][kr] = v.x;
            T2[ld4 + 1][kr] = v.y;
            T2[ld4 + 2][kr] = v.z;
            T2[ld4 + 3][kr] = v.w;
        }
        __syncthreads();

        float s[4][4];
#pragma unroll
        for (int i = 0; i < 4; i++)
#pragma unroll
            for (int j = 0; j < 4; j++) s[i][j] = 0.f;

#pragma unroll
        for (int d = 0; d < 64; d++) {
            float4 qa = *(const float4*)&T1[d][rm];
            float4 kb = *(const float4*)&T2[d][cn];
            float qv[4] = {qa.x, qa.y, qa.z, qa.w};
            float kv[4] = {kb.x, kb.y, kb.z, kb.w};
#pragma unroll
            for (int i = 0; i < 4; i++)
#pragma unroll
                for (int j = 0; j < 4; j++) s[i][j] += qv[i] * kv[j];
        }

        // mask + scale
        int mv[4];
#pragma unroll
        for (int j = 0; j < 4; j++) mv[j] = mask[b * SEQ + k0 + cn + j];
#pragma unroll
        for (int i = 0; i < 4; i++)
#pragma unroll
            for (int j = 0; j < 4; j++)
                s[i][j] = (mv[j] == 0) ? NEGV : s[i][j] * SCALEF;

        // write raw scores
#pragma unroll
        for (int i = 0; i < 4; i++) {
            float4 v = make_float4(s[i][0], s[i][1], s[i][2], s[i][3]);
            *(float4*)(attnbase + (size_t)(rm + i) * SEQ + k0 + cn) = v;
        }

        // online max / sumexp per row (reduce across the 16 tx lanes via shfl)
#pragma unroll
        for (int i = 0; i < 4; i++) {
            float tmax = fmaxf(fmaxf(s[i][0], s[i][1]), fmaxf(s[i][2], s[i][3]));
#pragma unroll
            for (int off = 1; off < 16; off <<= 1)
                tmax = fmaxf(tmax, __shfl_xor_sync(0xffffffffu, tmax, off));
            float mo = mrow[rm + i];
            float nm = fmaxf(mo, tmax);
            float ts = expf(s[i][0] - nm) + expf(s[i][1] - nm)
                     + expf(s[i][2] - nm) + expf(s[i][3] - nm);
#pragma unroll
            for (int off = 1; off < 16; off <<= 1)
                ts += __shfl_xor_sync(0xffffffffu, ts, off);
            if (tx == 0) {
                lrow[rm + i] = lrow[rm + i] * expf(mo - nm) + ts;
                mrow[rm + i] = nm;
            }
        }
        __syncthreads();
    }

    // finalize row stats
    float mf[4], rl[4];
#pragma unroll
    for (int i = 0; i < 4; i++) {
        mf[i] = mrow[rm + i];
        rl[i] = 1.f / lrow[rm + i];
    }

    // ================= Phase 2 =================
    float o[4][4];
#pragma unroll
    for (int i = 0; i < 4; i++)
#pragma unroll
        for (int j = 0; j < 4; j++) o[i][j] = 0.f;

    for (int kt = 0; kt < 16; kt++) {
        const int k0 = kt * 64;
        // load V tile: T2[krow][c] (row-major, stride 68 keeps float4 alignment)
#pragma unroll
        for (int it = 0; it < 4; it++) {
            int kr = lr0 + it * 16;
            float4 v = *(const float4*)(qkv + ((size_t)(b * SEQ + k0 + kr)) * (3 * DMODEL)
                                        + 2 * DMODEL + h * DHEAD + ld4);
            *(float4*)&T2[kr][ld4] = v;
        }

        // re-read own raw scores, normalize, write probs, stage P transposed
#pragma unroll
        for (int i = 0; i < 4; i++) {
            float* ap = attnbase + (size_t)(rm + i) * SEQ + k0 + cn;
            float4 sv = *(const float4*)ap;
            float4 p;
            p.x = expf(sv.x - mf[i]) * rl[i];
            p.y = expf(sv.y - mf[i]) * rl[i];
            p.z = expf(sv.z - mf[i]) * rl[i];
            p.w = expf(sv.w - mf[i]) * rl[i];
            *(float4*)ap = p;
            T1[cn + 0][rm + i] = p.x;
            T1[cn + 1][rm + i] = p.y;
            T1[cn + 2][rm + i] = p.z;
            T1[cn + 3][rm + i] = p.w;
        }
        __syncthreads();

        // O += P @ V
#pragma unroll
        for (int k = 0; k < 64; k++) {
            float4 pa = *(const float4*)&T1[k][rm];
            float4 vb = *(const float4*)&T2[k][cn];
            float pv[4] = {pa.x, pa.y, pa.z, pa.w};
            float vv[4] = {vb.x, vb.y, vb.z, vb.w};
#pragma unroll
            for (int i = 0; i < 4; i++)
#pragma unroll
                for (int j = 0; j < 4; j++) o[i][j] += pv[i] * vv[j];
        }
        __syncthreads();
    }

    // write ctx in [b, n, d] layout (d = h*DHEAD + c)
#pragma unroll
    for (int i = 0; i < 4; i++) {
        float4 v = make_float4(o[i][0], o[i][1], o[i][2], o[i][3]);
        *(float4*)(ctx + ((size_t)(b * SEQ + q0 + rm + i)) * DMODEL + h * DHEAD + cn) = v;
    }
}

// ---------------------------------------------------------------------------
extern "C" void kernel_launch(void* const* d_in, const int* in_sizes, int n_in,
                              void* d_out, int out_size)
{
    const float* x      = (const float*)d_in[0];
    const int*   mask   = (const int*)d_in[1];
    const float* w_qkv  = (const float*)d_in[2];
    const float* w_out  = (const float*)d_in[3];
    const float* b_out  = (const float*)d_in[4];

    float* out  = (float*)d_out;
    float* attn = out + (size_t)BDIM * SEQ * DMODEL;   // tuple (out, attn) concatenated

    float* qkv = nullptr;
    float* ctx = nullptr;
    cudaGetSymbolAddress((void**)&qkv, g_qkv);
    cudaGetSymbolAddress((void**)&ctx, g_ctx);

    // 1) qkv = x @ w_qkv        [8192,1024] x [1024,3072]
    {
        dim3 grid(3 * DMODEL / 128, BDIM * SEQ / 128);
        sgemm_kernel<<<grid, 256>>>(x, w_qkv, qkv, nullptr,
                                    BDIM * SEQ, 3 * DMODEL, DMODEL);
    }

    // 2) attention: writes attn (normalized) and ctx
    {
        dim3 grid(SEQ / 64, BDIM * NHEAD);
        attn_kernel<<<grid, 256>>>(qkv, mask, attn, ctx);
    }

    // 3) out = ctx @ w_out + b_out   [8192,1024] x [1024,1024]
    {
        dim3 grid(DMODEL / 128, BDIM * SEQ / 128);
        sgemm_kernel<<<grid, 256>>>(ctx, w_out, out, b_out,
                                    BDIM * SEQ, DMODEL, DMODEL);
    }
}

// round 2
// speedup vs baseline: 1.8232x; 1.8232x over previous
#include <cuda_runtime.h>
#include <cuda_bf16.h>
#include <math.h>
#include <stdint.h>

#define BDIM   8
#define SEQ    1024
#define DMODEL 1024
#define NHEAD  16
#define DHEAD  64
#define SCALEF 0.125f
#define NEGV   (-1e9f)

typedef __nv_bfloat16  bf16;
typedef __nv_bfloat162 bf162;

#define MROWS ((size_t)BDIM * SEQ)

// ---- scratch (device globals; no runtime alloc) ----
__device__ bf16 g_xh[MROWS * DMODEL],        g_xl[MROWS * DMODEL];
__device__ bf16 g_wqt_h[(size_t)3*DMODEL*DMODEL], g_wqt_l[(size_t)3*DMODEL*DMODEL];
__device__ bf16 g_wot_h[(size_t)DMODEL*DMODEL],   g_wot_l[(size_t)DMODEL*DMODEL];
__device__ bf16 g_qkvh[MROWS * 3*DMODEL],    g_qkvl[MROWS * 3*DMODEL];
__device__ bf16 g_ctxh[MROWS * DMODEL],      g_ctxl[MROWS * DMODEL];

// ---------------- helpers ----------------
__device__ __forceinline__ uint32_t sptr(const void* p) {
    return (uint32_t)__cvta_generic_to_shared(p);
}
__device__ __forceinline__ void cpa16(void* s, const void* g) {
    asm volatile("cp.async.cg.shared.global [%0], [%1], 16;\n" :: "r"(sptr(s)), "l"(g));
}
__device__ __forceinline__ void cpcommit() { asm volatile("cp.async.commit_group;\n"); }
__device__ __forceinline__ void cpwait0()  { asm volatile("cp.async.wait_group 0;\n"); }

__device__ __forceinline__ void ldsm4(uint32_t* r, const void* p) {
    asm volatile("ldmatrix.sync.aligned.m8n8.x4.shared.b16 {%0,%1,%2,%3}, [%4];\n"
        : "=r"(r[0]), "=r"(r[1]), "=r"(r[2]), "=r"(r[3]) : "r"(sptr(p)));
}
__device__ __forceinline__ void ldsm2(uint32_t* r, const void* p) {
    asm volatile("ldmatrix.sync.aligned.m8n8.x2.shared.b16 {%0,%1}, [%2];\n"
        : "=r"(r[0]), "=r"(r[1]) : "r"(sptr(p)));
}
__device__ __forceinline__ void ldsm2t(uint32_t* r, const void* p) {
    asm volatile("ldmatrix.sync.aligned.m8n8.x2.trans.shared.b16 {%0,%1}, [%2];\n"
        : "=r"(r[0]), "=r"(r[1]) : "r"(sptr(p)));
}
__device__ __forceinline__ void mma16816(float* c, const uint32_t* a, const uint32_t* b) {
    asm volatile("mma.sync.aligned.m16n8k16.row.col.f32.bf16.bf16.f32 "
        "{%0,%1,%2,%3}, {%4,%5,%6,%7}, {%8,%9}, {%0,%1,%2,%3};\n"
        : "+f"(c[0]), "+f"(c[1]), "+f"(c[2]), "+f"(c[3])
        : "r"(a[0]), "r"(a[1]), "r"(a[2]), "r"(a[3]), "r"(b[0]), "r"(b[1]));
}
__device__ __forceinline__ void split1(float v, bf16& h, bf16& l) {
    h = __float2bfloat16_rn(v);
    l = __float2bfloat16_rn(v - __bfloat162float(h));
}

// ---------------- converters ----------------
__global__ void split_kernel(const float* __restrict__ in,
                             bf16* __restrict__ oh, bf16* __restrict__ ol, int n4)
{
    int i = blockIdx.x * blockDim.x + threadIdx.x;
    if (i >= n4) return;
    float4 v = ((const float4*)in)[i];
    bf16 h0,l0,h1,l1,h2,l2,h3,l3;
    split1(v.x,h0,l0); split1(v.y,h1,l1); split1(v.z,h2,l2); split1(v.w,h3,l3);
    ((bf162*)oh)[2*i]   = __halves2bfloat162(h0,h1);
    ((bf162*)oh)[2*i+1] = __halves2bfloat162(h2,h3);
    ((bf162*)ol)[2*i]   = __halves2bfloat162(l0,l1);
    ((bf162*)ol)[2*i+1] = __halves2bfloat162(l2,l3);
}

// in: [K][N] fp32  ->  out: [N][K] bf16 hi/lo
__global__ void transpose_split(const float* __restrict__ in,
                                bf16* __restrict__ oh, bf16* __restrict__ ol,
                                int K, int N)
{
    __shared__ float t[32][33];
    int k0 = blockIdx.y * 32, n0 = blockIdx.x * 32;
    int tx = threadIdx.x, ty = threadIdx.y;
#pragma unroll
    for (int i = 0; i < 4; i++)
        t[ty + 8*i][tx] = in[(size_t)(k0 + ty + 8*i) * N + n0 + tx];
    __syncthreads();
#pragma unroll
    for (int i = 0; i < 4; i++) {
        float v = t[tx][ty + 8*i];
        bf16 h, l; split1(v, h, l);
        size_t o = (size_t)(n0 + ty + 8*i) * K + k0 + tx;
        oh[o] = h; ol[o] = l;
    }
}

// ---------------- GEMM: C[M,N] = A[M,K] @ Bt[N,K]^T (bf16 split, 3-term) ----------------
// A: [M][K] bf16 hi/lo, Bt: [N][K] bf16 hi/lo. Outputs fp32 and/or bf16 hi/lo.
__global__ __launch_bounds__(256)
void mma_gemm(const bf16* __restrict__ Ah, const bf16* __restrict__ Al,
              const bf16* __restrict__ Bh, const bf16* __restrict__ Bl,
              float* __restrict__ Cf, bf16* __restrict__ Ch, bf16* __restrict__ Cl,
              const float* __restrict__ bias, int M, int N, int K)
{
    extern __shared__ __align__(16) bf16 sm[];
    bf16* sA = sm;              // [2 stage][2 hl][128*40]
    bf16* sB = sm + 4 * 5120;   // same

    const int tid  = threadIdx.x;
    const int lane = tid & 31, wid = tid >> 5;
    const int mw = wid >> 2, nw = wid & 3;
    const int bm = blockIdx.y * 128, bn = blockIdx.x * 128;

    float acc[4][4][4];
#pragma unroll
    for (int a = 0; a < 4; a++)
#pragma unroll
        for (int b = 0; b < 4; b++)
#pragma unroll
            for (int c = 0; c < 4; c++) acc[a][b][c] = 0.f;

    auto stage = [&](int st, int k0) {
#pragma unroll
        for (int i = 0; i < 2; i++) {
            int s = tid + i * 256;
            int r = s >> 2, c = (s & 3) * 8;
            size_t ga = (size_t)(bm + r) * K + k0 + c;
            cpa16(&sA[(st*2+0)*5120 + r*40 + c], Ah + ga);
            cpa16(&sA[(st*2+1)*5120 + r*40 + c], Al + ga);
            size_t gb = (size_t)(bn + r) * K + k0 + c;
            cpa16(&sB[(st*2+0)*5120 + r*40 + c], Bh + gb);
            cpa16(&sB[(st*2+1)*5120 + r*40 + c], Bl + gb);
        }
        cpcommit();
    };

    const int NT = K / 32;
    stage(0, 0);

    for (int kt = 0; kt < NT; kt++) {
        int st = kt & 1;
        cpwait0();
        __syncthreads();
        if (kt + 1 < NT) stage(st ^ 1, (kt + 1) * 32);

#pragma unroll
        for (int ks = 0; ks < 2; ks++) {
            uint32_t afh[4][4], afl[4][4], bfh[4][2], bfl[4][2];
#pragma unroll
            for (int mf = 0; mf < 4; mf++) {
                int off = (mw*64 + mf*16 + (lane & 15)) * 40 + ks*16 + (lane >> 4) * 8;
                ldsm4(afh[mf], &sA[(st*2+0)*5120 + off]);
                ldsm4(afl[mf], &sA[(st*2+1)*5120 + off]);
            }
#pragma unroll
            for (int nf = 0; nf < 4; nf++) {
                int li = lane & 15;
                int off = (nw*32 + nf*8 + (li & 7)) * 40 + ks*16 + (li >> 3) * 8;
                ldsm2(bfh[nf], &sB[(st*2+0)*5120 + off]);
                ldsm2(bfl[nf], &sB[(st*2+1)*5120 + off]);
            }
#pragma unroll
            for (int mf = 0; mf < 4; mf++)
#pragma unroll
                for (int nf = 0; nf < 4; nf++) {
                    mma16816(acc[mf][nf], afh[mf], bfh[nf]);
                    mma16816(acc[mf][nf], afh[mf], bfl[nf]);
                    mma16816(acc[mf][nf], afl[mf], bfh[nf]);
                }
        }
        __syncthreads();
    }

    // epilogue
#pragma unroll
    for (int mf = 0; mf < 4; mf++)
#pragma unroll
        for (int nf = 0; nf < 4; nf++)
#pragma unroll
            for (int c = 0; c < 2; c++) {
                int row = bm + mw*64 + mf*16 + (lane >> 2) + c*8;
                int col = bn + nw*32 + nf*8  + 2*(lane & 3);
                float v0 = acc[mf][nf][2*c+0];
                float v1 = acc[mf][nf][2*c+1];
                if (bias) { v0 += bias[col]; v1 += bias[col+1]; }
                if (Cf) *(float2*)&Cf[(size_t)row * N + col] = make_float2(v0, v1);
                if (Ch) {
                    bf16 h0,l0,h1,l1; split1(v0,h0,l0); split1(v1,h1,l1);
                    *(bf162*)&Ch[(size_t)row * N + col] = __halves2bfloat162(h0,h1);
                    *(bf162*)&Cl[(size_t)row * N + col] = __halves2bfloat162(l0,l1);
                }
            }
}

// ---------------- attention (flash-style 2-pass, bf16-split MMA) ----------------
// block: (q-tile of 64, b*h). 8 warps as 2(m) x 4(n).
#define SQE 4608   // 64*72 elements per tile array
__global__ __launch_bounds__(256)
void attn_mma(const bf16* __restrict__ qh, const bf16* __restrict__ ql,
              const int* __restrict__ mask,
              float* __restrict__ attn,
              bf16* __restrict__ ctxh, bf16* __restrict__ ctxl)
{
    extern __shared__ __align__(16) char smraw[];
    bf16*  sQh = (bf16*)smraw;                  // 64x72
    bf16*  sQl = sQh + SQE;
    bf16*  sK  = sQl + SQE;                     // [2 st][2 hl][64*72]
    bf16*  sV  = sK + 4*SQE;                    // [2 st][2 hl][64*72]
    bf16*  sPh = sV + 4*SQE;
    bf16*  sPl = sPh + SQE;
    float* mrow  = (float*)(sPl + SQE);         // 64
    float* lrow  = mrow + 64;                   // 64
    float* red   = lrow + 64;                   // 64*4
    int*   smask = (int*)(red + 256);           // [2][64]

    const int tid = threadIdx.x, lane = tid & 31, wid = tid >> 5;
    const int mw = wid >> 2, nw = wid & 3;
    const int q0 = blockIdx.x * 64;
    const int bh = blockIdx.y, b = bh >> 4, h = bh & 15;
    const size_t RS = 3 * DMODEL;

    // ---- stage Q, build Q fragments (held in regs for both phases) ----
    for (int s = tid; s < 512; s += 256) {
        int r = s >> 3, c = (s & 7) * 8;
        size_t g = (size_t)(b*SEQ + q0 + r) * RS + h*DHEAD + c;
        cpa16(&sQh[r*72 + c], qh + g);
        cpa16(&sQl[r*72 + c], ql + g);
    }
    cpcommit(); cpwait0();
    if (tid < 64) { mrow[tid] = -INFINITY; lrow[tid] = 0.f; }
    __syncthreads();

    uint32_t qfh[2][4][4], qfl[2][4][4];
#pragma unroll
    for (int mf = 0; mf < 2; mf++)
#pragma unroll
        for (int ks = 0; ks < 4; ks++) {
            int off = (mw*32 + mf*16 + (lane & 15)) * 72 + ks*16 + (lane >> 4) * 8;
            ldsm4(qfh[mf][ks], &sQh[off]);
            ldsm4(qfl[mf][ks], &sQl[off]);
        }

    auto stageK = [&](int st, int kt) {
        int k0 = kt * 64;
        if (tid < 64) smask[st*64 + tid] = mask[b*SEQ + k0 + tid];
        for (int s = tid; s < 512; s += 256) {
            int r = s >> 3, c = (s & 7) * 8;
            size_t g = (size_t)(b*SEQ + k0 + r) * RS + DMODEL + h*DHEAD + c;
            cpa16(&sK[(st*2+0)*SQE + r*72 + c], qh + g);
            cpa16(&sK[(st*2+1)*SQE + r*72 + c], ql + g);
        }
        cpcommit();
    };
    auto stageKV = [&](int st, int kt) {
        int k0 = kt * 64;
        if (tid < 64) smask[st*64 + tid] = mask[b*SEQ + k0 + tid];
        for (int s = tid; s < 512; s += 256) {
            int r = s >> 3, c = (s & 7) * 8;
            size_t gk = (size_t)(b*SEQ + k0 + r) * RS + DMODEL     + h*DHEAD + c;
            size_t gv = (size_t)(b*SEQ + k0 + r) * RS + 2*DMODEL   + h*DHEAD + c;
            cpa16(&sK[(st*2+0)*SQE + r*72 + c], qh + gk);
            cpa16(&sK[(st*2+1)*SQE + r*72 + c], ql + gk);
            cpa16(&sV[(st*2+0)*SQE + r*72 + c], qh + gv);
            cpa16(&sV[(st*2+1)*SQE + r*72 + c], ql + gv);
        }
        cpcommit();
    };

    // computes masked+scaled S tile into sacc (reads sK buffers + smask)
    auto computeS = [&](int st, float sacc[2][2][4]) {
#pragma unroll
        for (int a = 0; a < 2; a++)
#pragma unroll
            for (int n = 0; n < 2; n++)
#pragma unroll
                for (int c = 0; c < 4; c++) sacc[a][n][c] = 0.f;
#pragma unroll
        for (int ks = 0; ks < 4; ks++) {
            uint32_t kbh[2][2], kbl[2][2];
#pragma unroll
            for (int nf = 0; nf < 2; nf++) {
                int li = lane & 15;
                int off = (nw*16 + nf*8 + (li & 7)) * 72 + ks*16 + (li >> 3) * 8;
                ldsm2(kbh[nf], &sK[(st*2+0)*SQE + off]);
                ldsm2(kbl[nf], &sK[(st*2+1)*SQE + off]);
            }
#pragma unroll
            for (int mf = 0; mf < 2; mf++)
#pragma unroll
                for (int nf = 0; nf < 2; nf++) {
                    mma16816(sacc[mf][nf], qfh[mf][ks], kbh[nf]);
                    mma16816(sacc[mf][nf], qfh[mf][ks], kbl[nf]);
                    mma16816(sacc[mf][nf], qfl[mf][ks], kbh[nf]);
                }
        }
        // mask + scale
#pragma unroll
        for (int nf = 0; nf < 2; nf++)
#pragma unroll
            for (int ci = 0; ci < 2; ci++) {
                int col = nw*16 + nf*8 + 2*(lane & 3) + ci;
                int mv  = smask[st*64 + col];
#pragma unroll
                for (int mf = 0; mf < 2; mf++)
#pragma unroll
                    for (int c = 0; c < 2; c++) {
                        float v = sacc[mf][nf][2*c+ci];
                        sacc[mf][nf][2*c+ci] = mv ? v * SCALEF : NEGV;
                    }
            }
    };

    // ================= phase 1: row max / sumexp =================
    stageK(0, 0);
    for (int kt = 0; kt < 16; kt++) {
        int st = kt & 1;
        cpwait0();
        __syncthreads();
        if (kt + 1 < 16) stageK(st ^ 1, kt + 1);

        float sacc[2][2][4];
        computeS(st, sacc);

        // per-row partial max
#pragma unroll
        for (int mf = 0; mf < 2; mf++)
#pragma unroll
            for (int c = 0; c < 2; c++) {
                float v = fmaxf(fmaxf(sacc[mf][0][2*c], sacc[mf][0][2*c+1]),
                                fmaxf(sacc[mf][1][2*c], sacc[mf][1][2*c+1]));
                v = fmaxf(v, __shfl_xor_sync(0xffffffffu, v, 1));
                v = fmaxf(v, __shfl_xor_sync(0xffffffffu, v, 2));
                if ((lane & 3) == 0)
                    red[(mw*32 + mf*16 + c*8 + (lane >> 2)) * 4 + nw] = v;
            }
        __syncthreads();
        if (tid < 64) {
            float t = fmaxf(fmaxf(red[tid*4], red[tid*4+1]),
                            fmaxf(red[tid*4+2], red[tid*4+3]));
            float mo = mrow[tid], mn = fmaxf(mo, t);
            mrow[tid] = mn;
            lrow[tid] *= __expf(mo - mn);
        }
        __syncthreads();
#pragma unroll
        for (int mf = 0; mf < 2; mf++)
#pragma unroll
            for (int c = 0; c < 2; c++) {
                int row = mw*32 + mf*16 + c*8 + (lane >> 2);
                float m = mrow[row];
                float s = __expf(sacc[mf][0][2*c]   - m) + __expf(sacc[mf][0][2*c+1] - m)
                        + __expf(sacc[mf][1][2*c]   - m) + __expf(sacc[mf][1][2*c+1] - m);
                s += __shfl_xor_sync(0xffffffffu, s, 1);
                s += __shfl_xor_sync(0xffffffffu, s, 2);
                if ((lane & 3) == 0) red[row*4 + nw] = s;
            }
        __syncthreads();
        if (tid < 64)
            lrow[tid] += red[tid*4] + red[tid*4+1] + red[tid*4+2] + red[tid*4+3];
    }
    __syncthreads();
    if (tid < 64) lrow[tid] = 1.f / lrow[tid];   // lrow now holds reciprocal
    __syncthreads();

    // ================= phase 2: recompute S, write attn, O = P@V =================
    float oacc[2][2][4];
#pragma unroll
    for (int a = 0; a < 2; a++)
#pragma unroll
        for (int n = 0; n < 2; n++)
#pragma unroll
            for (int c = 0; c < 4; c++) oacc[a][n][c] = 0.f;

    stageKV(0, 0);
    for (int kt = 0; kt < 16; kt++) {
        int st = kt & 1;
        cpwait0();
        __syncthreads();
        if (kt + 1 < 16) stageKV(st ^ 1, kt + 1);

        float sacc[2][2][4];
        computeS(st, sacc);

        // normalize, write attn, stage P to smem
#pragma unroll
        for (int mf = 0; mf < 2; mf++)
#pragma unroll
            for (int c = 0; c < 2; c++) {
                int row = mw*32 + mf*16 + c*8 + (lane >> 2);
                float m = mrow[row], rl = lrow[row];
#pragma unroll
                for (int nf = 0; nf < 2; nf++) {
                    int col = nw*16 + nf*8 + 2*(lane & 3);
                    float p0 = __expf(sacc[mf][nf][2*c]   - m) * rl;
                    float p1 = __expf(sacc[mf][nf][2*c+1] - m) * rl;
                    *(float2*)&attn[((size_t)bh*SEQ + q0 + row) * SEQ + kt*64 + col]
                        = make_float2(p0, p1);
                    bf16 h0,l0,h1,l1; split1(p0,h0,l0); split1(p1,h1,l1);
                    *(bf162*)&sPh[row*72 + col] = __halves2bfloat162(h0,h1);
                    *(bf162*)&sPl[row*72 + col] = __halves2bfloat162(l0,l1);
                }
            }
        __syncthreads();

        // O += P @ V
#pragma unroll
        for (int ks = 0; ks < 4; ks++) {
            uint32_t pfh[2][4], pfl[2][4], vbh[2][2], vbl[2][2];
#pragma unroll
            for (int mf = 0; mf < 2; mf++) {
                int off = (mw*32 + mf*16 + (lane & 15)) * 72 + ks*16 + (lane >> 4) * 8;
                ldsm4(pfh[mf], &sPh[off]);
                ldsm4(pfl[mf], &sPl[off]);
            }
#pragma unroll
            for (int nf = 0; nf < 2; nf++) {
                int li = lane & 15;
                int off = (ks*16 + li) * 72 + nw*16 + nf*8;
                ldsm2t(vbh[nf], &sV[(st*2+0)*SQE + off]);
                ldsm2t(vbl[nf], &sV[(st*2+1)*SQE + off]);
            }
#pragma unroll
            for (int mf = 0; mf < 2; mf++)
#pragma unroll
                for (int nf = 0; nf < 2; nf++) {
                    mma16816(oacc[mf][nf], pfh[mf], vbh[nf]);
                    mma16816(oacc[mf][nf], pfh[mf], vbl[nf]);
                    mma16816(oacc[mf][nf], pfl[mf], vbh[nf]);
                }
        }
        __syncthreads();
    }

    // write ctx (bf16 hi/lo) in [b*SEQ + n][D] layout
#pragma unroll
    for (int mf = 0; mf < 2; mf++)
#pragma unroll
        for (int nf = 0; nf < 2; nf++)
#pragma unroll
            for (int c = 0; c < 2; c++) {
                int row = b*SEQ + q0 + mw*32 + mf*16 + c*8 + (lane >> 2);
                int col = h*DHEAD + nw*16 + nf*8 + 2*(lane & 3);
                float v0 = oacc[mf][nf][2*c], v1 = oacc[mf][nf][2*c+1];
                bf16 h0,l0,h1,l1; split1(v0,h0,l0); split1(v1,h1,l1);
                *(bf162*)&g_ctxh[(size_t)row*DMODEL + col] = __halves2bfloat162(h0,h1);
                *(bf162*)&g_ctxl[(size_t)row*DMODEL + col] = __halves2bfloat162(l0,l1);
            }
}

// ---------------- launcher ----------------
extern "C" void kernel_launch(void* const* d_in, const int* in_sizes, int n_in,
                              void* d_out, int out_size)
{
    const float* x     = (const float*)d_in[0];
    const int*   mask  = (const int*)d_in[1];
    const float* w_qkv = (const float*)d_in[2];
    const float* w_out = (const float*)d_in[3];
    const float* b_out = (const float*)d_in[4];

    float* out  = (float*)d_out;
    float* attn = out + MROWS * DMODEL;

    bf16 *xh, *xl, *wqh, *wql, *woh, *wol, *qkvh, *qkvl, *ctxh, *ctxl;
    cudaGetSymbolAddress((void**)&xh,  g_xh);  cudaGetSymbolAddress((void**)&xl,  g_xl);
    cudaGetSymbolAddress((void**)&wqh, g_wqt_h); cudaGetSymbolAddress((void**)&wql, g_wqt_l);
    cudaGetSymbolAddress((void**)&woh, g_wot_h); cudaGetSymbolAddress((void**)&wol, g_wot_l);
    cudaGetSymbolAddress((void**)&qkvh, g_qkvh); cudaGetSymbolAddress((void**)&qkvl, g_qkvl);
    cudaGetSymbolAddress((void**)&ctxh, g_ctxh); cudaGetSymbolAddress((void**)&ctxl, g_ctxl);

    cudaFuncSetAttribute(mma_gemm, cudaFuncAttributeMaxDynamicSharedMemorySize, 81920);
    cudaFuncSetAttribute(attn_mma, cudaFuncAttributeMaxDynamicSharedMemorySize, 120832);

    // 1) split x
    {
        int n4 = (int)(MROWS * DMODEL / 4);
        split_kernel<<<(n4 + 255) / 256, 256>>>(x, xh, xl, n4);
    }
    // 2) transpose+split weights
    transpose_split<<<dim3(3*DMODEL/32, DMODEL/32), dim3(32,8)>>>(w_qkv, wqh, wql, DMODEL, 3*DMODEL);
    transpose_split<<<dim3(DMODEL/32,   DMODEL/32), dim3(32,8)>>>(w_out, woh, wol, DMODEL, DMODEL);

    // 3) qkv = x @ w_qkv  (bf16 hi/lo out)
    mma_gemm<<<dim3(3*DMODEL/128, (int)(MROWS/128)), 256, 81920>>>(
        xh, xl, wqh, wql, nullptr, qkvh, qkvl, nullptr,
        (int)MROWS, 3*DMODEL, DMODEL);

    // 4) attention -> attn (fp32) + ctx (bf16 hi/lo)
    attn_mma<<<dim3(SEQ/64, BDIM*NHEAD), 256, 120832>>>(
        qkvh, qkvl, mask, attn, ctxh, ctxl);

    // 5) out = ctx @ w_out + b_out  (fp32 out)
    mma_gemm<<<dim3(DMODEL/128, (int)(MROWS/128)), 256, 81920>>>(
        ctxh, ctxl, woh, wol, out, nullptr, nullptr, b_out,
        (int)MROWS, DMODEL, DMODEL);
}

// round 4
// speedup vs baseline: 1.8941x; 1.0389x over previous
#include <cuda_runtime.h>
#include <cuda_bf16.h>
#include <math.h>
#include <stdint.h>

#define BDIM   8
#define SEQ    1024
#define DMODEL 1024
#define NHEAD  16
#define DHEAD  64
#define QT     128

typedef __nv_bfloat16  bf16;
typedef __nv_bfloat162 bf162;

#define MROWS ((size_t)BDIM * SEQ)

// single dynamic-smem symbol shared by all kernels
extern __shared__ __align__(16) char dynsm[];

// ---- scratch (device globals; no runtime alloc) ----
__device__ bf16 g_xh[MROWS * DMODEL],        g_xl[MROWS * DMODEL];
__device__ bf16 g_wqt_h[(size_t)3*DMODEL*DMODEL], g_wqt_l[(size_t)3*DMODEL*DMODEL];
__device__ bf16 g_wot_h[(size_t)DMODEL*DMODEL],   g_wot_l[(size_t)DMODEL*DMODEL];
__device__ bf16 g_qkvh[MROWS * 3*DMODEL],    g_qkvl[MROWS * 3*DMODEL];
__device__ bf16 g_ctxh[MROWS * DMODEL],      g_ctxl[MROWS * DMODEL];

// ---------------- helpers ----------------
__device__ __forceinline__ uint32_t sptr(const void* p) {
    return (uint32_t)__cvta_generic_to_shared(p);
}
__device__ __forceinline__ void cpa16(void* s, const void* g) {
    asm volatile("cp.async.cg.shared.global [%0], [%1], 16;\n" :: "r"(sptr(s)), "l"(g));
}
__device__ __forceinline__ void cpcommit() { asm volatile("cp.async.commit_group;\n"); }
__device__ __forceinline__ void cpwait0()  { asm volatile("cp.async.wait_group 0;\n"); }

__device__ __forceinline__ void ldsm4(uint32_t* r, const void* p) {
    asm volatile("ldmatrix.sync.aligned.m8n8.x4.shared.b16 {%0,%1,%2,%3}, [%4];\n"
        : "=r"(r[0]), "=r"(r[1]), "=r"(r[2]), "=r"(r[3]) : "r"(sptr(p)));
}
__device__ __forceinline__ void ldsm4t(uint32_t* r, const void* p) {
    asm volatile("ldmatrix.sync.aligned.m8n8.x4.trans.shared.b16 {%0,%1,%2,%3}, [%4];\n"
        : "=r"(r[0]), "=r"(r[1]), "=r"(r[2]), "=r"(r[3]) : "r"(sptr(p)));
}
__device__ __forceinline__ void ldsm2(uint32_t* r, const void* p) {
    asm volatile("ldmatrix.sync.aligned.m8n8.x2.shared.b16 {%0,%1}, [%2];\n"
        : "=r"(r[0]), "=r"(r[1]) : "r"(sptr(p)));
}
__device__ __forceinline__ void mma16816(float* c, const uint32_t* a, const uint32_t* b) {
    asm volatile("mma.sync.aligned.m16n8k16.row.col.f32.bf16.bf16.f32 "
        "{%0,%1,%2,%3}, {%4,%5,%6,%7}, {%8,%9}, {%0,%1,%2,%3};\n"
        : "+f"(c[0]), "+f"(c[1]), "+f"(c[2]), "+f"(c[3])
        : "r"(a[0]), "r"(a[1]), "r"(a[2]), "r"(a[3]), "r"(b[0]), "r"(b[1]));
}
__device__ __forceinline__ void split1(float v, bf16& h, bf16& l) {
    h = __float2bfloat16_rn(v);
    l = __float2bfloat16_rn(v - __bfloat162float(h));
}
__device__ __forceinline__ uint32_t pack2(bf16 lo, bf16 hi) {
    return (uint32_t)__bfloat16_as_ushort(lo) | ((uint32_t)__bfloat16_as_ushort(hi) << 16);
}
// split two floats, pack hi-pair and lo-pair
__device__ __forceinline__ void split_pack2(float v0, float v1, uint32_t& ph, uint32_t& pl) {
    bf16 h0,l0,h1,l1;
    split1(v0,h0,l0); split1(v1,h1,l1);
    ph = pack2(h0,h1);
    pl = pack2(l0,l1);
}
// 2^y via magic rounding + degree-5 poly (FMA pipe only, no MUFU). |y| < 30.
__device__ __forceinline__ float fexp2p(float y) {
    float t = y + 12582912.f;          // 2^23 + 2^22 magic (RN)
    float n = t - 12582912.f;
    float f = y - n;
    float p = 0.00133335581f;
    p = fmaf(p, f, 0.00961812911f);
    p = fmaf(p, f, 0.05550410866f);
    p = fmaf(p, f, 0.24022650696f);
    p = fmaf(p, f, 0.69314718056f);
    p = fmaf(p, f, 1.0f);
    int e = (__float_as_int(t) - 0x4B400000 + 127) << 23;
    return __int_as_float(e) * p;
}
#define Y_SCALE 0.18033688011112042f   // 0.125 * log2(e)

// ---------------- converters ----------------
__global__ void split_kernel(const float* __restrict__ in,
                             bf16* __restrict__ oh, bf16* __restrict__ ol, int n4)
{
    int i = blockIdx.x * blockDim.x + threadIdx.x;
    if (i >= n4) return;
    float4 v = ((const float4*)in)[i];
    uint32_t ph0, pl0, ph1, pl1;
    split_pack2(v.x, v.y, ph0, pl0);
    split_pack2(v.z, v.w, ph1, pl1);
    ((uint32_t*)oh)[2*i]   = ph0;
    ((uint32_t*)oh)[2*i+1] = ph1;
    ((uint32_t*)ol)[2*i]   = pl0;
    ((uint32_t*)ol)[2*i+1] = pl1;
}

__global__ void transpose_split(const float* __restrict__ in,
                                bf16* __restrict__ oh, bf16* __restrict__ ol,
                                int K, int N)
{
    __shared__ float t[32][33];
    int k0 = blockIdx.y * 32, n0 = blockIdx.x * 32;
    int tx = threadIdx.x, ty = threadIdx.y;
#pragma unroll
    for (int i = 0; i < 4; i++)
        t[ty + 8*i][tx] = in[(size_t)(k0 + ty + 8*i) * N + n0 + tx];
    __syncthreads();
#pragma unroll
    for (int i = 0; i < 4; i++) {
        float v = t[tx][ty + 8*i];
        bf16 h, l; split1(v, h, l);
        size_t o = (size_t)(n0 + ty + 8*i) * K + k0 + tx;
        oh[o] = h; ol[o] = l;
    }
}

// ---------------- GEMM (bf16 split, 3-term), 2 CTAs/SM ----------------
__global__ __launch_bounds__(256, 2)
void mma_gemm(const bf16* __restrict__ Ah, const bf16* __restrict__ Al,
              const bf16* __restrict__ Bh, const bf16* __restrict__ Bl,
              float* __restrict__ Cf, bf16* __restrict__ Ch, bf16* __restrict__ Cl,
              const float* __restrict__ bias, int M, int N, int K)
{
    bf16* sA = (bf16*)dynsm;
    bf16* sB = (bf16*)dynsm + 4 * 5120;

    const int tid  = threadIdx.x;
    const int lane = tid & 31, wid = tid >> 5;
    const int mw = wid >> 2, nw = wid & 3;
    const int bm = blockIdx.y * 128, bn = blockIdx.x * 128;

    float acc[4][4][4];
#pragma unroll
    for (int a = 0; a < 4; a++)
#pragma unroll
        for (int b = 0; b < 4; b++)
#pragma unroll
            for (int c = 0; c < 4; c++) acc[a][b][c] = 0.f;

    auto stage = [&](int st, int k0) {
#pragma unroll
        for (int i = 0; i < 2; i++) {
            int s = tid + i * 256;
            int r = s >> 2, c = (s & 3) * 8;
            size_t ga = (size_t)(bm + r) * K + k0 + c;
            cpa16(&sA[(st*2+0)*5120 + r*40 + c], Ah + ga);
            cpa16(&sA[(st*2+1)*5120 + r*40 + c], Al + ga);
            size_t gb = (size_t)(bn + r) * K + k0 + c;
            cpa16(&sB[(st*2+0)*5120 + r*40 + c], Bh + gb);
            cpa16(&sB[(st*2+1)*5120 + r*40 + c], Bl + gb);
        }
        cpcommit();
    };

    const int NT = K / 32;
    stage(0, 0);

    for (int kt = 0; kt < NT; kt++) {
        int st = kt & 1;
        cpwait0();
        __syncthreads();
        if (kt + 1 < NT) stage(st ^ 1, (kt + 1) * 32);

#pragma unroll
        for (int ks = 0; ks < 2; ks++) {
            uint32_t afh[4][4], afl[4][4], bfh[4][2], bfl[4][2];
#pragma unroll
            for (int mf = 0; mf < 4; mf++) {
                int off = (mw*64 + mf*16 + (lane & 15)) * 40 + ks*16 + (lane >> 4) * 8;
                ldsm4(afh[mf], &sA[(st*2+0)*5120 + off]);
                ldsm4(afl[mf], &sA[(st*2+1)*5120 + off]);
            }
#pragma unroll
            for (int nf = 0; nf < 4; nf++) {
                int li = lane & 15;
                int off = (nw*32 + nf*8 + (li & 7)) * 40 + ks*16 + (li >> 3) * 8;
                ldsm2(bfh[nf], &sB[(st*2+0)*5120 + off]);
                ldsm2(bfl[nf], &sB[(st*2+1)*5120 + off]);
            }
#pragma unroll
            for (int mf = 0; mf < 4; mf++)
#pragma unroll
                for (int nf = 0; nf < 4; nf++) {
                    mma16816(acc[mf][nf], afh[mf], bfh[nf]);
                    mma16816(acc[mf][nf], afh[mf], bfl[nf]);
                    mma16816(acc[mf][nf], afl[mf], bfh[nf]);
                }
        }
        __syncthreads();
    }

#pragma unroll
    for (int mf = 0; mf < 4; mf++)
#pragma unroll
        for (int nf = 0; nf < 4; nf++)
#pragma unroll
            for (int c = 0; c < 2; c++) {
                int row = bm + mw*64 + mf*16 + (lane >> 2) + c*8;
                int col = bn + nw*32 + nf*8  + 2*(lane & 3);
                float v0 = acc[mf][nf][2*c+0];
                float v1 = acc[mf][nf][2*c+1];
                if (bias) { v0 += bias[col]; v1 += bias[col+1]; }
                if (Cf) *(float2*)&Cf[(size_t)row * N + col] = make_float2(v0, v1);
                if (Ch) {
                    uint32_t ph, pl;
                    split_pack2(v0, v1, ph, pl);
                    *(uint32_t*)&Ch[(size_t)row * N + col] = ph;
                    *(uint32_t*)&Cl[(size_t)row * N + col] = pl;
                }
            }
}

// ---------------- one-pass attention ----------------
// grid (SEQ/128, B*H), 256 threads = 8 warps, each warp owns 16 query rows.
#define KBUF 4608   // 64*72 elements per K/V buffer
__global__ __launch_bounds__(256)
void attn_one(const bf16* __restrict__ qh, const bf16* __restrict__ ql,
              const int* __restrict__ mask,
              float* __restrict__ attn,
              bf16* __restrict__ ctxh, bf16* __restrict__ ctxl)
{
    char* sm = dynsm;
    bf16*  sQh  = (bf16*)sm;                    // 128*72
    bf16*  sQl  = (bf16*)(sm + 18432);
    bf16*  sKb  = (bf16*)(sm + 36864);          // [2 st][2 hl][64*72]
    bf16*  sVb  = (bf16*)(sm + 73728);
    int*   smask = (int*)(sm + 110592);         // [2][64]
    float* lrec  = (float*)(sm + 111104);       // [128]

    const int tid = threadIdx.x, lane = tid & 31, w = tid >> 5;
    const int q0 = blockIdx.x * QT;
    const int bh = blockIdx.y, b = bh >> 4, h = bh & 15;
    const size_t RS = 3 * DMODEL;

    // stage Q
    for (int s = tid; s < 1024; s += 256) {
        int r = s >> 3, c = (s & 7) * 8;
        size_t g = (size_t)(b*SEQ + q0 + r) * RS + h*DHEAD + c;
        cpa16(&sQh[r*72 + c], qh + g);
        cpa16(&sQl[r*72 + c], ql + g);
    }
    cpcommit();

    auto stageKV = [&](int st, int kt) {
        int k0 = kt * 64;
        if (tid < 64) smask[st*64 + tid] = mask[b*SEQ + k0 + tid];
        for (int s = tid; s < 512; s += 256) {
            int r = s >> 3, c = (s & 7) * 8;
            size_t gk = (size_t)(b*SEQ + k0 + r) * RS + DMODEL + h*DHEAD + c;
            size_t gv = gk + DMODEL;
            cpa16(&sKb[(st*2+0)*KBUF + r*72 + c], qh + gk);
            cpa16(&sKb[(st*2+1)*KBUF + r*72 + c], ql + gk);
            cpa16(&sVb[(st*2+0)*KBUF + r*72 + c], qh + gv);
            cpa16(&sVb[(st*2+1)*KBUF + r*72 + c], ql + gv);
        }
        cpcommit();
    };

    stageKV(0, 0);
    cpwait0();
    __syncthreads();

    // Q fragments, held for the whole kernel
    uint32_t qfh[4][4], qfl[4][4];
#pragma unroll
    for (int ks = 0; ks < 4; ks++) {
        int off = (w*16 + (lane & 15)) * 72 + ks*16 + (lane >> 4) * 8;
        ldsm4(qfh[ks], &sQh[off]);
        ldsm4(qfl[ks], &sQl[off]);
    }

    float oacc[8][4];
#pragma unroll
    for (int nf = 0; nf < 8; nf++)
#pragma unroll
        for (int c = 0; c < 4; c++) oacc[nf][c] = 0.f;
    float rs0 = 0.f, rs1 = 0.f;

    const int rlo = lane >> 2, qq = lane & 3;
    const size_t abase = ((size_t)bh * SEQ + q0) * SEQ;

    for (int kt = 0; kt < 16; kt++) {
        int st = kt & 1;
        if (kt) { cpwait0(); __syncthreads(); }
        if (kt + 1 < 16) stageKV(st ^ 1, kt + 1);

        // ---- S = Q K^T (per-warp m16 x n64) ----
        float sacc[8][4];
#pragma unroll
        for (int nf = 0; nf < 8; nf++)
#pragma unroll
            for (int c = 0; c < 4; c++) sacc[nf][c] = 0.f;

#pragma unroll
        for (int ks = 0; ks < 4; ks++) {
            uint32_t kh[8][2], kl[8][2];
#pragma unroll
            for (int p = 0; p < 4; p++) {
                int g = lane >> 3;
                int off = (p*16 + (g & 1)*8 + (lane & 7)) * 72 + ks*16 + (g >> 1) * 8;
                uint32_t r4[4];
                ldsm4(r4, &sKb[(st*2+0)*KBUF + off]);
                kh[2*p][0] = r4[0]; kh[2*p+1][0] = r4[1];
                kh[2*p][1] = r4[2]; kh[2*p+1][1] = r4[3];
                ldsm4(r4, &sKb[(st*2+1)*KBUF + off]);
                kl[2*p][0] = r4[0]; kl[2*p+1][0] = r4[1];
                kl[2*p][1] = r4[2]; kl[2*p+1][1] = r4[3];
            }
#pragma unroll
            for (int nf = 0; nf < 8; nf++) {
                mma16816(sacc[nf], qfh[ks], kh[nf]);
                mma16816(sacc[nf], qfh[ks], kl[nf]);
                mma16816(sacc[nf], qfl[ks], kh[nf]);
            }
        }

        // ---- exp (poly), mask, store unnormalized p, pack P frags ----
        uint32_t pah[4][4], pal[4][4];
#pragma unroll
        for (int p = 0; p < 4; p++) {
            float pv[2][4];   // [even/odd nf][c]
#pragma unroll
            for (int eo = 0; eo < 2; eo++) {
                int nf = 2*p + eo;
                int c0 = nf*8 + 2*qq;
                int m0 = smask[st*64 + c0];
                int m1 = smask[st*64 + c0 + 1];
                float e0 = m0 ? fexp2p(sacc[nf][0] * Y_SCALE) : 0.f;
                float e1 = m1 ? fexp2p(sacc[nf][1] * Y_SCALE) : 0.f;
                float e2 = m0 ? fexp2p(sacc[nf][2] * Y_SCALE) : 0.f;
                float e3 = m1 ? fexp2p(sacc[nf][3] * Y_SCALE) : 0.f;
                pv[eo][0] = e0; pv[eo][1] = e1; pv[eo][2] = e2; pv[eo][3] = e3;
                rs0 += e0 + e1;
                rs1 += e2 + e3;
                // store unnormalized probabilities
                size_t a0 = abase + (size_t)(w*16 + rlo) * SEQ + kt*64 + c0;
                size_t a1 = a0 + 8 * SEQ;
                *(float2*)&attn[a0] = make_float2(e0, e1);
                *(float2*)&attn[a1] = make_float2(e2, e3);
            }
            // pack to A fragments (hi/lo split)
            split_pack2(pv[0][0], pv[0][1], pah[p][0], pal[p][0]);
            split_pack2(pv[0][2], pv[0][3], pah[p][1], pal[p][1]);
            split_pack2(pv[1][0], pv[1][1], pah[p][2], pal[p][2]);
            split_pack2(pv[1][2], pv[1][3], pah[p][3], pal[p][3]);
        }

        // ---- O += P @ V ----
#pragma unroll
        for (int pk = 0; pk < 4; pk++) {
            uint32_t vh[8][2], vl[8][2];
#pragma unroll
            for (int p = 0; p < 4; p++) {
                int g = lane >> 3;
                int off = (pk*16 + (g & 1)*8 + (lane & 7)) * 72 + (2*p + (g >> 1)) * 8;
                uint32_t r4[4];
                ldsm4t(r4, &sVb[(st*2+0)*KBUF + off]);
                vh[2*p][0] = r4[0]; vh[2*p][1] = r4[1];
                vh[2*p+1][0] = r4[2]; vh[2*p+1][1] = r4[3];
                ldsm4t(r4, &sVb[(st*2+1)*KBUF + off]);
                vl[2*p][0] = r4[0]; vl[2*p][1] = r4[1];
                vl[2*p+1][0] = r4[2]; vl[2*p+1][1] = r4[3];
            }
#pragma unroll
            for (int nf = 0; nf < 8; nf++) {
                mma16816(oacc[nf], pah[pk], vh[nf]);
                mma16816(oacc[nf], pah[pk], vl[nf]);
                mma16816(oacc[nf], pal[pk], vh[nf]);
            }
        }
    }

    // ---- finalize: l, ctx, normalize epilogue ----
    rs0 += __shfl_xor_sync(0xffffffffu, rs0, 1);
    rs0 += __shfl_xor_sync(0xffffffffu, rs0, 2);
    rs1 += __shfl_xor_sync(0xffffffffu, rs1, 1);
    rs1 += __shfl_xor_sync(0xffffffffu, rs1, 2);
    float ri0 = 1.f / rs0, ri1 = 1.f / rs1;
    if ((lane & 3) == 0) {
        lrec[w*16 + rlo]     = ri0;
        lrec[w*16 + rlo + 8] = ri1;
    }

    const size_t row0 = (size_t)(b*SEQ + q0 + w*16 + rlo);
#pragma unroll
    for (int nf = 0; nf < 8; nf++) {
        int col = h*DHEAD + nf*8 + 2*qq;
        uint32_t ph, pl;
        split_pack2(oacc[nf][0] * ri0, oacc[nf][1] * ri0, ph, pl);
        *(uint32_t*)&ctxh[row0*DMODEL + col] = ph;
        *(uint32_t*)&ctxl[row0*DMODEL + col] = pl;
        split_pack2(oacc[nf][2] * ri1, oacc[nf][3] * ri1, ph, pl);
        *(uint32_t*)&ctxh[(row0+8)*DMODEL + col] = ph;
        *(uint32_t*)&ctxl[(row0+8)*DMODEL + col] = pl;
    }

    __syncthreads();   // lrec visible + all attn stores in-block visible

    // normalize this block's attn region (L2-hot re-read)
    for (int s = tid; s < QT * 256; s += 256) {
        int r = s >> 8, c = (s & 255) * 4;
        float sc = lrec[r];
        float4* p = (float4*)(attn + abase + (size_t)r * SEQ + c);
        float4 v = *p;
        v.x *= sc; v.y *= sc; v.z *= sc; v.w *= sc;
        *p = v;
    }
}

// ---------------- launcher ----------------
extern "C" void kernel_launch(void* const* d_in, const int* in_sizes, int n_in,
                              void* d_out, int out_size)
{
    const float* x     = (const float*)d_in[0];
    const int*   mask  = (const int*)d_in[1];
    const float* w_qkv = (const float*)d_in[2];
    const float* w_out = (const float*)d_in[3];
    const float* b_out = (const float*)d_in[4];

    float* out  = (float*)d_out;
    float* attn = out + MROWS * DMODEL;

    bf16 *xh, *xl, *wqh, *wql, *woh, *wol, *qkvh, *qkvl, *ctxh, *ctxl;
    cudaGetSymbolAddress((void**)&xh,  g_xh);  cudaGetSymbolAddress((void**)&xl,  g_xl);
    cudaGetSymbolAddress((void**)&wqh, g_wqt_h); cudaGetSymbolAddress((void**)&wql, g_wqt_l);
    cudaGetSymbolAddress((void**)&woh, g_wot_h); cudaGetSymbolAddress((void**)&wol, g_wot_l);
    cudaGetSymbolAddress((void**)&qkvh, g_qkvh); cudaGetSymbolAddress((void**)&qkvl, g_qkvl);
    cudaGetSymbolAddress((void**)&ctxh, g_ctxh); cudaGetSymbolAddress((void**)&ctxl, g_ctxl);

    cudaFuncSetAttribute(mma_gemm, cudaFuncAttributeMaxDynamicSharedMemorySize, 81920);
    cudaFuncSetAttribute(attn_one, cudaFuncAttributeMaxDynamicSharedMemorySize, 111616);

    {
        int n4 = (int)(MROWS * DMODEL / 4);
        split_kernel<<<(n4 + 255) / 256, 256>>>(x, xh, xl, n4);
    }
    transpose_split<<<dim3(3*DMODEL/32, DMODEL/32), dim3(32,8)>>>(w_qkv, wqh, wql, DMODEL, 3*DMODEL);
    transpose_split<<<dim3(DMODEL/32,   DMODEL/32), dim3(32,8)>>>(w_out, woh, wol, DMODEL, DMODEL);

    mma_gemm<<<dim3(3*DMODEL/128, (int)(MROWS/128)), 256, 81920>>>(
        xh, xl, wqh, wql, nullptr, qkvh, qkvl, nullptr,
        (int)MROWS, 3*DMODEL, DMODEL);

    attn_one<<<dim3(SEQ/QT, BDIM*NHEAD), 256, 111616>>>(
        qkvh, qkvl, mask, attn, ctxh, ctxl);

    mma_gemm<<<dim3(DMODEL/128, (int)(MROWS/128)), 256, 81920>>>(
        ctxh, ctxl, woh, wol, out, nullptr, nullptr, b_out,
        (int)MROWS, DMODEL, DMODEL);
}

// round 5
// speedup vs baseline: 2.1685x; 1.1448x over previous
#include <cuda_runtime.h>
#include <cuda_bf16.h>
#include <math.h>
#include <stdint.h>

#define BDIM   8
#define SEQ    1024
#define DMODEL 1024
#define NHEAD  16
#define DHEAD  64
#define QT     128

typedef __nv_bfloat16  bf16;
typedef __nv_bfloat162 bf162;

#define MROWS ((size_t)BDIM * SEQ)

// single dynamic-smem symbol shared by all kernels
extern __shared__ __align__(16) char dynsm[];

// ---- scratch (device globals; no runtime alloc) ----
__device__ bf16 g_xh[MROWS * DMODEL],        g_xl[MROWS * DMODEL];
__device__ bf16 g_wqt_h[(size_t)3*DMODEL*DMODEL], g_wqt_l[(size_t)3*DMODEL*DMODEL];
__device__ bf16 g_wot_h[(size_t)DMODEL*DMODEL],   g_wot_l[(size_t)DMODEL*DMODEL];
__device__ bf16 g_qkvh[MROWS * 3*DMODEL],    g_qkvl[MROWS * 3*DMODEL];
__device__ bf16 g_ctxh[MROWS * DMODEL],      g_ctxl[MROWS * DMODEL];

// ---------------- helpers ----------------
__device__ __forceinline__ uint32_t sptr(const void* p) {
    return (uint32_t)__cvta_generic_to_shared(p);
}
__device__ __forceinline__ void cpa16(void* s, const void* g) {
    asm volatile("cp.async.cg.shared.global [%0], [%1], 16;\n" :: "r"(sptr(s)), "l"(g));
}
__device__ __forceinline__ void cpcommit() { asm volatile("cp.async.commit_group;\n"); }
__device__ __forceinline__ void cpwait0()  { asm volatile("cp.async.wait_group 0;\n"); }

__device__ __forceinline__ void ldsm4(uint32_t* r, const void* p) {
    asm volatile("ldmatrix.sync.aligned.m8n8.x4.shared.b16 {%0,%1,%2,%3}, [%4];\n"
        : "=r"(r[0]), "=r"(r[1]), "=r"(r[2]), "=r"(r[3]) : "r"(sptr(p)));
}
__device__ __forceinline__ void ldsm4t(uint32_t* r, const void* p) {
    asm volatile("ldmatrix.sync.aligned.m8n8.x4.trans.shared.b16 {%0,%1,%2,%3}, [%4];\n"
        : "=r"(r[0]), "=r"(r[1]), "=r"(r[2]), "=r"(r[3]) : "r"(sptr(p)));
}
__device__ __forceinline__ void mma16816(float* c, const uint32_t* a, const uint32_t* b) {
    asm volatile("mma.sync.aligned.m16n8k16.row.col.f32.bf16.bf16.f32 "
        "{%0,%1,%2,%3}, {%4,%5,%6,%7}, {%8,%9}, {%0,%1,%2,%3};\n"
        : "+f"(c[0]), "+f"(c[1]), "+f"(c[2]), "+f"(c[3])
        : "r"(a[0]), "r"(a[1]), "r"(a[2]), "r"(a[3]), "r"(b[0]), "r"(b[1]));
}
__device__ __forceinline__ void split1(float v, bf16& h, bf16& l) {
    h = __float2bfloat16_rn(v);
    l = __float2bfloat16_rn(v - __bfloat162float(h));
}
__device__ __forceinline__ uint32_t pack2(bf16 lo, bf16 hi) {
    return (uint32_t)__bfloat16_as_ushort(lo) | ((uint32_t)__bfloat16_as_ushort(hi) << 16);
}
__device__ __forceinline__ void split_pack2(float v0, float v1, uint32_t& ph, uint32_t& pl) {
    bf16 h0,l0,h1,l1;
    split1(v0,h0,l0); split1(v1,h1,l1);
    ph = pack2(h0,h1);
    pl = pack2(l0,l1);
}
// 2^y via magic rounding + degree-5 poly (FMA pipe only, no MUFU). |y| < 30.
__device__ __forceinline__ float fexp2p(float y) {
    float t = y + 12582912.f;          // 2^23 + 2^22 magic (RN)
    float n = t - 12582912.f;
    float f = y - n;
    float p = 0.00133335581f;
    p = fmaf(p, f, 0.00961812911f);
    p = fmaf(p, f, 0.05550410866f);
    p = fmaf(p, f, 0.24022650696f);
    p = fmaf(p, f, 0.69314718056f);
    p = fmaf(p, f, 1.0f);
    int e = (__float_as_int(t) - 0x4B400000 + 127) << 23;
    return __int_as_float(e) * p;
}
#define Y_SCALE 0.18033688011112042f   // 0.125 * log2(e)

// ---------------- converters ----------------
__global__ void split_kernel(const float* __restrict__ in,
                             bf16* __restrict__ oh, bf16* __restrict__ ol, int n4)
{
    int i = blockIdx.x * blockDim.x + threadIdx.x;
    if (i >= n4) return;
    float4 v = ((const float4*)in)[i];
    uint32_t ph0, pl0, ph1, pl1;
    split_pack2(v.x, v.y, ph0, pl0);
    split_pack2(v.z, v.w, ph1, pl1);
    ((uint32_t*)oh)[2*i]   = ph0;
    ((uint32_t*)oh)[2*i+1] = ph1;
    ((uint32_t*)ol)[2*i]   = pl0;
    ((uint32_t*)ol)[2*i+1] = pl1;
}

__global__ void transpose_split(const float* __restrict__ in,
                                bf16* __restrict__ oh, bf16* __restrict__ ol,
                                int K, int N)
{
    __shared__ float t[32][33];
    int k0 = blockIdx.y * 32, n0 = blockIdx.x * 32;
    int tx = threadIdx.x, ty = threadIdx.y;
#pragma unroll
    for (int i = 0; i < 4; i++)
        t[ty + 8*i][tx] = in[(size_t)(k0 + ty + 8*i) * N + n0 + tx];
    __syncthreads();
#pragma unroll
    for (int i = 0; i < 4; i++) {
        float v = t[tx][ty + 8*i];
        bf16 h, l; split1(v, h, l);
        size_t o = (size_t)(n0 + ty + 8*i) * K + k0 + tx;
        oh[o] = h; ol[o] = l;
    }
}

// ---------------- GEMM (bf16 split, 3-term), 2 CTAs/SM ----------------
__global__ __launch_bounds__(256, 2)
void mma_gemm(const bf16* __restrict__ Ah, const bf16* __restrict__ Al,
              const bf16* __restrict__ Bh, const bf16* __restrict__ Bl,
              float* __restrict__ Cf, bf16* __restrict__ Ch, bf16* __restrict__ Cl,
              const float* __restrict__ bias, int M, int N, int K)
{
    bf16* sA = (bf16*)dynsm;
    bf16* sB = (bf16*)dynsm + 4 * 5120;

    const int tid  = threadIdx.x;
    const int lane = tid & 31, wid = tid >> 5;
    const int mw = wid >> 2, nw = wid & 3;
    const int bm = blockIdx.y * 128, bn = blockIdx.x * 128;

    float acc[4][4][4];
#pragma unroll
    for (int a = 0; a < 4; a++)
#pragma unroll
        for (int b = 0; b < 4; b++)
#pragma unroll
            for (int c = 0; c < 4; c++) acc[a][b][c] = 0.f;

    auto stage = [&](int st, int k0) {
#pragma unroll
        for (int i = 0; i < 2; i++) {
            int s = tid + i * 256;
            int r = s >> 2, c = (s & 3) * 8;
            size_t ga = (size_t)(bm + r) * K + k0 + c;
            cpa16(&sA[(st*2+0)*5120 + r*40 + c], Ah + ga);
            cpa16(&sA[(st*2+1)*5120 + r*40 + c], Al + ga);
            size_t gb = (size_t)(bn + r) * K + k0 + c;
            cpa16(&sB[(st*2+0)*5120 + r*40 + c], Bh + gb);
            cpa16(&sB[(st*2+1)*5120 + r*40 + c], Bl + gb);
        }
        cpcommit();
    };

    const int NT = K / 32;
    stage(0, 0);

    for (int kt = 0; kt < NT; kt++) {
        int st = kt & 1;
        cpwait0();
        __syncthreads();
        if (kt + 1 < NT) stage(st ^ 1, (kt + 1) * 32);

#pragma unroll
        for (int ks = 0; ks < 2; ks++) {
            uint32_t afh[4][4], afl[4][4], bfh[4][2], bfl[4][2];
#pragma unroll
            for (int mf = 0; mf < 4; mf++) {
                int off = (mw*64 + mf*16 + (lane & 15)) * 40 + ks*16 + (lane >> 4) * 8;
                ldsm4(afh[mf], &sA[(st*2+0)*5120 + off]);
                ldsm4(afl[mf], &sA[(st*2+1)*5120 + off]);
            }
            {
                int g = lane >> 3;
#pragma unroll
                for (int pp = 0; pp < 2; pp++) {
                    int off = (nw*32 + pp*16 + (g & 1)*8 + (lane & 7)) * 40
                            + ks*16 + (g >> 1) * 8;
                    uint32_t r4[4], s4[4];
                    ldsm4(r4, &sB[(st*2+0)*5120 + off]);
                    ldsm4(s4, &sB[(st*2+1)*5120 + off]);
                    bfh[2*pp][0]   = r4[0]; bfh[2*pp][1]   = r4[2];
                    bfh[2*pp+1][0] = r4[1]; bfh[2*pp+1][1] = r4[3];
                    bfl[2*pp][0]   = s4[0]; bfl[2*pp][1]   = s4[2];
                    bfl[2*pp+1][0] = s4[1]; bfl[2*pp+1][1] = s4[3];
                }
            }
#pragma unroll
            for (int mf = 0; mf < 4; mf++)
#pragma unroll
                for (int nf = 0; nf < 4; nf++) {
                    mma16816(acc[mf][nf], afh[mf], bfh[nf]);
                    mma16816(acc[mf][nf], afh[mf], bfl[nf]);
                    mma16816(acc[mf][nf], afl[mf], bfh[nf]);
                }
        }
        __syncthreads();
    }

#pragma unroll
    for (int mf = 0; mf < 4; mf++)
#pragma unroll
        for (int nf = 0; nf < 4; nf++)
#pragma unroll
            for (int c = 0; c < 2; c++) {
                int row = bm + mw*64 + mf*16 + (lane >> 2) + c*8;
                int col = bn + nw*32 + nf*8  + 2*(lane & 3);
                float v0 = acc[mf][nf][2*c+0];
                float v1 = acc[mf][nf][2*c+1];
                if (bias) { v0 += bias[col]; v1 += bias[col+1]; }
                if (Cf) *(float2*)&Cf[(size_t)row * N + col] = make_float2(v0, v1);
                if (Ch) {
                    uint32_t ph, pl;
                    split_pack2(v0, v1, ph, pl);
                    *(uint32_t*)&Ch[(size_t)row * N + col] = ph;
                    *(uint32_t*)&Cl[(size_t)row * N + col] = pl;
                }
            }
}

// ---------------- one-pass attention, 2 CTAs/SM ----------------
// grid (SEQ/128, B*H), 256 threads = 8 warps, each warp owns 16 query rows.
#define KBUF 4608   // 64*72 elements per K/V buffer
__global__ __launch_bounds__(256, 2)
void attn_one(const bf16* __restrict__ qh, const bf16* __restrict__ ql,
              const int* __restrict__ mask,
              float* __restrict__ attn,
              bf16* __restrict__ ctxh, bf16* __restrict__ ctxl)
{
    char* sm = dynsm;
    bf16*  sQh  = (bf16*)sm;                    // 128*72
    bf16*  sQl  = (bf16*)(sm + 18432);
    bf16*  sKb  = (bf16*)(sm + 36864);          // [2 st][2 hl][64*72]
    bf16*  sVb  = (bf16*)(sm + 73728);
    int*   smask = (int*)(sm + 110592);         // [2][64]
    float* lrec  = (float*)(sm + 111104);       // [128]

    const int tid = threadIdx.x, lane = tid & 31, w = tid >> 5;
    const int q0 = blockIdx.x * QT;
    const int bh = blockIdx.y, b = bh >> 4, h = bh & 15;
    const size_t RS = 3 * DMODEL;

    // stage Q
    for (int s = tid; s < 1024; s += 256) {
        int r = s >> 3, c = (s & 7) * 8;
        size_t g = (size_t)(b*SEQ + q0 + r) * RS + h*DHEAD + c;
        cpa16(&sQh[r*72 + c], qh + g);
        cpa16(&sQl[r*72 + c], ql + g);
    }
    cpcommit();

    auto stageKV = [&](int st, int kt) {
        int k0 = kt * 64;
        if (tid < 64) smask[st*64 + tid] = mask[b*SEQ + k0 + tid];
        for (int s = tid; s < 512; s += 256) {
            int r = s >> 3, c = (s & 7) * 8;
            size_t gk = (size_t)(b*SEQ + k0 + r) * RS + DMODEL + h*DHEAD + c;
            size_t gv = gk + DMODEL;
            cpa16(&sKb[(st*2+0)*KBUF + r*72 + c], qh + gk);
            cpa16(&sKb[(st*2+1)*KBUF + r*72 + c], ql + gk);
            cpa16(&sVb[(st*2+0)*KBUF + r*72 + c], qh + gv);
            cpa16(&sVb[(st*2+1)*KBUF + r*72 + c], ql + gv);
        }
        cpcommit();
    };

    stageKV(0, 0);
    cpwait0();
    __syncthreads();

    float oacc[8][4];
#pragma unroll
    for (int nf = 0; nf < 8; nf++)
#pragma unroll
        for (int c = 0; c < 4; c++) oacc[nf][c] = 0.f;
    float rs0 = 0.f, rs1 = 0.f;

    const int rlo = lane >> 2, qq = lane & 3;
    const int g8 = lane >> 3;
    const size_t abase = ((size_t)bh * SEQ + q0) * SEQ;

    for (int kt = 0; kt < 16; kt++) {
        int st = kt & 1;
        if (kt) { cpwait0(); __syncthreads(); }
        if (kt + 1 < 16) stageKV(st ^ 1, kt + 1);

        // ---- S = Q K^T (per-warp m16 x n64), minimal transients ----
        float sacc[8][4];
#pragma unroll
        for (int nf = 0; nf < 8; nf++)
#pragma unroll
            for (int c = 0; c < 4; c++) sacc[nf][c] = 0.f;

#pragma unroll
        for (int ks = 0; ks < 4; ks++) {
            uint32_t q4h[4], q4l[4];
            int qoff = (w*16 + (lane & 15)) * 72 + ks*16 + (lane >> 4) * 8;
            ldsm4(q4h, &sQh[qoff]);
            ldsm4(q4l, &sQl[qoff]);
#pragma unroll
            for (int p = 0; p < 4; p++) {
                int off = (p*16 + (g8 & 1)*8 + (lane & 7)) * 72 + ks*16 + (g8 >> 1) * 8;
                uint32_t r4[4], s4[4];
                ldsm4(r4, &sKb[(st*2+0)*KBUF + off]);
                ldsm4(s4, &sKb[(st*2+1)*KBUF + off]);
                uint32_t b0[2] = {r4[0], r4[2]}, b1[2] = {r4[1], r4[3]};
                uint32_t c0[2] = {s4[0], s4[2]}, c1[2] = {s4[1], s4[3]};
                mma16816(sacc[2*p],   q4h, b0);
                mma16816(sacc[2*p],   q4h, c0);
                mma16816(sacc[2*p],   q4l, b0);
                mma16816(sacc[2*p+1], q4h, b1);
                mma16816(sacc[2*p+1], q4h, c1);
                mma16816(sacc[2*p+1], q4l, b1);
            }
        }

        // ---- exp (poly), mask, store unnormalized p in place ----
#pragma unroll
        for (int nf = 0; nf < 8; nf++) {
            int c0i = nf*8 + 2*qq;
            int m0 = smask[st*64 + c0i];
            int m1 = smask[st*64 + c0i + 1];
            float e0 = m0 ? fexp2p(sacc[nf][0] * Y_SCALE) : 0.f;
            float e1 = m1 ? fexp2p(sacc[nf][1] * Y_SCALE) : 0.f;
            float e2 = m0 ? fexp2p(sacc[nf][2] * Y_SCALE) : 0.f;
            float e3 = m1 ? fexp2p(sacc[nf][3] * Y_SCALE) : 0.f;
            sacc[nf][0] = e0; sacc[nf][1] = e1; sacc[nf][2] = e2; sacc[nf][3] = e3;
            rs0 += e0 + e1;
            rs1 += e2 + e3;
            size_t a0 = abase + (size_t)(w*16 + rlo) * SEQ + kt*64 + c0i;
            *(float2*)&attn[a0]           = make_float2(e0, e1);
            *(float2*)&attn[a0 + 8*SEQ]   = make_float2(e2, e3);
        }

        // ---- O += P @ V (a-frags built per pk, V loaded per p) ----
#pragma unroll
        for (int pk = 0; pk < 4; pk++) {
            uint32_t ah[4], al[4];
            split_pack2(sacc[2*pk][0],   sacc[2*pk][1],   ah[0], al[0]);
            split_pack2(sacc[2*pk][2],   sacc[2*pk][3],   ah[1], al[1]);
            split_pack2(sacc[2*pk+1][0], sacc[2*pk+1][1], ah[2], al[2]);
            split_pack2(sacc[2*pk+1][2], sacc[2*pk+1][3], ah[3], al[3]);
#pragma unroll
            for (int p = 0; p < 4; p++) {
                int off = (pk*16 + (g8 & 1)*8 + (lane & 7)) * 72 + (2*p + (g8 >> 1)) * 8;
                uint32_t r4[4], s4[4];
                ldsm4t(r4, &sVb[(st*2+0)*KBUF + off]);
                ldsm4t(s4, &sVb[(st*2+1)*KBUF + off]);
                uint32_t v0[2] = {r4[0], r4[1]}, v1[2] = {r4[2], r4[3]};
                uint32_t u0[2] = {s4[0], s4[1]}, u1[2] = {s4[2], s4[3]};
                mma16816(oacc[2*p],   ah, v0);
                mma16816(oacc[2*p],   ah, u0);
                mma16816(oacc[2*p],   al, v0);
                mma16816(oacc[2*p+1], ah, v1);
                mma16816(oacc[2*p+1], ah, u1);
                mma16816(oacc[2*p+1], al, v1);
            }
        }
    }

    // ---- finalize: l, ctx, normalize epilogue ----
    rs0 += __shfl_xor_sync(0xffffffffu, rs0, 1);
    rs0 += __shfl_xor_sync(0xffffffffu, rs0, 2);
    rs1 += __shfl_xor_sync(0xffffffffu, rs1, 1);
    rs1 += __shfl_xor_sync(0xffffffffu, rs1, 2);
    float ri0 = 1.f / rs0, ri1 = 1.f / rs1;
    if ((lane & 3) == 0) {
        lrec[w*16 + rlo]     = ri0;
        lrec[w*16 + rlo + 8] = ri1;
    }

    const size_t row0 = (size_t)(b*SEQ + q0 + w*16 + rlo);
#pragma unroll
    for (int nf = 0; nf < 8; nf++) {
        int col = h*DHEAD + nf*8 + 2*qq;
        uint32_t ph, pl;
        split_pack2(oacc[nf][0] * ri0, oacc[nf][1] * ri0, ph, pl);
        *(uint32_t*)&ctxh[row0*DMODEL + col] = ph;
        *(uint32_t*)&ctxl[row0*DMODEL + col] = pl;
        split_pack2(oacc[nf][2] * ri1, oacc[nf][3] * ri1, ph, pl);
        *(uint32_t*)&ctxh[(row0+8)*DMODEL + col] = ph;
        *(uint32_t*)&ctxl[(row0+8)*DMODEL + col] = pl;
    }

    __syncthreads();   // lrec visible + all attn stores in-block visible

    // normalize this block's attn region (L2-hot re-read)
    for (int s = tid; s < QT * 256; s += 256) {
        int r = s >> 8, c = (s & 255) * 4;
        float sc = lrec[r];
        float4* p = (float4*)(attn + abase + (size_t)r * SEQ + c);
        float4 v = *p;
        v.x *= sc; v.y *= sc; v.z *= sc; v.w *= sc;
        *p = v;
    }
}

// ---------------- launcher ----------------
extern "C" void kernel_launch(void* const* d_in, const int* in_sizes, int n_in,
                              void* d_out, int out_size)
{
    const float* x     = (const float*)d_in[0];
    const int*   mask  = (const int*)d_in[1];
    const float* w_qkv = (const float*)d_in[2];
    const float* w_out = (const float*)d_in[3];
    const float* b_out = (const float*)d_in[4];

    float* out  = (float*)d_out;
    float* attn = out + MROWS * DMODEL;

    bf16 *xh, *xl, *wqh, *wql, *woh, *wol, *qkvh, *qkvl, *ctxh, *ctxl;
    cudaGetSymbolAddress((void**)&xh,  g_xh);  cudaGetSymbolAddress((void**)&xl,  g_xl);
    cudaGetSymbolAddress((void**)&wqh, g_wqt_h); cudaGetSymbolAddress((void**)&wql, g_wqt_l);
    cudaGetSymbolAddress((void**)&woh, g_wot_h); cudaGetSymbolAddress((void**)&wol, g_wot_l);
    cudaGetSymbolAddress((void**)&qkvh, g_qkvh); cudaGetSymbolAddress((void**)&qkvl, g_qkvl);
    cudaGetSymbolAddress((void**)&ctxh, g_ctxh); cudaGetSymbolAddress((void**)&ctxl, g_ctxl);

    cudaFuncSetAttribute(mma_gemm, cudaFuncAttributeMaxDynamicSharedMemorySize, 81920);
    cudaFuncSetAttribute(attn_one, cudaFuncAttributeMaxDynamicSharedMemorySize, 111616);

    {
        int n4 = (int)(MROWS * DMODEL / 4);
        split_kernel<<<(n4 + 255) / 256, 256>>>(x, xh, xl, n4);
    }
    transpose_split<<<dim3(3*DMODEL/32, DMODEL/32), dim3(32,8)>>>(w_qkv, wqh, wql, DMODEL, 3*DMODEL);
    transpose_split<<<dim3(DMODEL/32,   DMODEL/32), dim3(32,8)>>>(w_out, woh, wol, DMODEL, DMODEL);

    mma_gemm<<<dim3(3*DMODEL/128, (int)(MROWS/128)), 256, 81920>>>(
        xh, xl, wqh, wql, nullptr, qkvh, qkvl, nullptr,
        (int)MROWS, 3*DMODEL, DMODEL);

    attn_one<<<dim3(SEQ/QT, BDIM*NHEAD), 256, 111616>>>(
        qkvh, qkvl, mask, attn, ctxh, ctxl);

    mma_gemm<<<dim3(DMODEL/128, (int)(MROWS/128)), 256, 81920>>>(
        ctxh, ctxl, woh, wol, out, nullptr, nullptr, b_out,
        (int)MROWS, DMODEL, DMODEL);
}

// round 6
// speedup vs baseline: 2.4400x; 1.1252x over previous
#include <cuda_runtime.h>
#include <cuda_bf16.h>
#include <math.h>
#include <stdint.h>

#define BDIM   8
#define SEQ    1024
#define DMODEL 1024
#define NHEAD  16
#define DHEAD  64
#define QT     128

typedef __nv_bfloat16  bf16;
typedef __nv_bfloat162 bf162;

#define MROWS ((size_t)BDIM * SEQ)

// single dynamic-smem symbol shared by all kernels
extern __shared__ __align__(16) char dynsm[];

// ---- scratch (device globals; no runtime alloc) ----
__device__ bf16 g_xh[MROWS * DMODEL],        g_xl[MROWS * DMODEL];
__device__ bf16 g_wqt_h[(size_t)3*DMODEL*DMODEL], g_wqt_l[(size_t)3*DMODEL*DMODEL];
__device__ bf16 g_wot_h[(size_t)DMODEL*DMODEL],   g_wot_l[(size_t)DMODEL*DMODEL];
__device__ bf16 g_qkvh[MROWS * 3*DMODEL],    g_qkvl[MROWS * 3*DMODEL];
__device__ bf16 g_ctxh[MROWS * DMODEL],      g_ctxl[MROWS * DMODEL];

// ---------------- helpers ----------------
__device__ __forceinline__ uint32_t sptr(const void* p) {
    return (uint32_t)__cvta_generic_to_shared(p);
}
__device__ __forceinline__ void cpa16(void* s, const void* g) {
    asm volatile("cp.async.cg.shared.global [%0], [%1], 16;\n" :: "r"(sptr(s)), "l"(g));
}
__device__ __forceinline__ void cpcommit() { asm volatile("cp.async.commit_group;\n"); }
__device__ __forceinline__ void cpwait0()  { asm volatile("cp.async.wait_group 0;\n"); }

__device__ __forceinline__ void ldsm4(uint32_t* r, const void* p) {
    asm volatile("ldmatrix.sync.aligned.m8n8.x4.shared.b16 {%0,%1,%2,%3}, [%4];\n"
        : "=r"(r[0]), "=r"(r[1]), "=r"(r[2]), "=r"(r[3]) : "r"(sptr(p)));
}
__device__ __forceinline__ void ldsm4t(uint32_t* r, const void* p) {
    asm volatile("ldmatrix.sync.aligned.m8n8.x4.trans.shared.b16 {%0,%1,%2,%3}, [%4];\n"
        : "=r"(r[0]), "=r"(r[1]), "=r"(r[2]), "=r"(r[3]) : "r"(sptr(p)));
}
__device__ __forceinline__ void ldsm2(uint32_t* r, const void* p) {
    asm volatile("ldmatrix.sync.aligned.m8n8.x2.shared.b16 {%0,%1}, [%2];\n"
        : "=r"(r[0]), "=r"(r[1]) : "r"(sptr(p)));
}
__device__ __forceinline__ void mma16816(float* c, const uint32_t* a, const uint32_t* b) {
    asm volatile("mma.sync.aligned.m16n8k16.row.col.f32.bf16.bf16.f32 "
        "{%0,%1,%2,%3}, {%4,%5,%6,%7}, {%8,%9}, {%0,%1,%2,%3};\n"
        : "+f"(c[0]), "+f"(c[1]), "+f"(c[2]), "+f"(c[3])
        : "r"(a[0]), "r"(a[1]), "r"(a[2]), "r"(a[3]), "r"(b[0]), "r"(b[1]));
}
__device__ __forceinline__ void split1(float v, bf16& h, bf16& l) {
    h = __float2bfloat16_rn(v);
    l = __float2bfloat16_rn(v - __bfloat162float(h));
}
__device__ __forceinline__ uint32_t pack2(bf16 lo, bf16 hi) {
    return (uint32_t)__bfloat16_as_ushort(lo) | ((uint32_t)__bfloat16_as_ushort(hi) << 16);
}
__device__ __forceinline__ void split_pack2(float v0, float v1, uint32_t& ph, uint32_t& pl) {
    bf16 h0,l0,h1,l1;
    split1(v0,h0,l0); split1(v1,h1,l1);
    ph = pack2(h0,h1);
    pl = pack2(l0,l1);
}
// 2^y via magic rounding + degree-5 poly (FMA pipe only, no MUFU). |y| < 30.
__device__ __forceinline__ float fexp2p(float y) {
    float t = y + 12582912.f;          // 2^23 + 2^22 magic (RN)
    float n = t - 12582912.f;
    float f = y - n;
    float p = 0.00133335581f;
    p = fmaf(p, f, 0.00961812911f);
    p = fmaf(p, f, 0.05550410866f);
    p = fmaf(p, f, 0.24022650696f);
    p = fmaf(p, f, 0.69314718056f);
    p = fmaf(p, f, 1.0f);
    int e = (__float_as_int(t) - 0x4B400000 + 127) << 23;
    return __int_as_float(e) * p;
}
#define Y_SCALE 0.18033688011112042f   // 0.125 * log2(e)

// ---------------- converters ----------------
__global__ void split_kernel(const float* __restrict__ in,
                             bf16* __restrict__ oh, bf16* __restrict__ ol, int n4)
{
    int i = blockIdx.x * blockDim.x + threadIdx.x;
    if (i >= n4) return;
    float4 v = ((const float4*)in)[i];
    uint32_t ph0, pl0, ph1, pl1;
    split_pack2(v.x, v.y, ph0, pl0);
    split_pack2(v.z, v.w, ph1, pl1);
    ((uint32_t*)oh)[2*i]   = ph0;
    ((uint32_t*)oh)[2*i+1] = ph1;
    ((uint32_t*)ol)[2*i]   = pl0;
    ((uint32_t*)ol)[2*i+1] = pl1;
}

__global__ void transpose_split(const float* __restrict__ in,
                                bf16* __restrict__ oh, bf16* __restrict__ ol,
                                int K, int N)
{
    __shared__ float t[32][33];
    int k0 = blockIdx.y * 32, n0 = blockIdx.x * 32;
    int tx = threadIdx.x, ty = threadIdx.y;
#pragma unroll
    for (int i = 0; i < 4; i++)
        t[ty + 8*i][tx] = in[(size_t)(k0 + ty + 8*i) * N + n0 + tx];
    __syncthreads();
#pragma unroll
    for (int i = 0; i < 4; i++) {
        float v = t[tx][ty + 8*i];
        bf16 h, l; split1(v, h, l);
        size_t o = (size_t)(n0 + ty + 8*i) * K + k0 + tx;
        oh[o] = h; ol[o] = l;
    }
}

// ---------------- GEMM (bf16 split, 3-term), 2 CTAs/SM ----------------
__global__ __launch_bounds__(256, 2)
void mma_gemm(const bf16* __restrict__ Ah, const bf16* __restrict__ Al,
              const bf16* __restrict__ Bh, const bf16* __restrict__ Bl,
              float* __restrict__ Cf, bf16* __restrict__ Ch, bf16* __restrict__ Cl,
              const float* __restrict__ bias, int M, int N, int K)
{
    bf16* sA = (bf16*)dynsm;
    bf16* sB = (bf16*)dynsm + 4 * 5120;

    const int tid  = threadIdx.x;
    const int lane = tid & 31, wid = tid >> 5;
    const int mw = wid >> 2, nw = wid & 3;
    const int bm = blockIdx.y * 128, bn = blockIdx.x * 128;

    float acc[4][4][4];
#pragma unroll
    for (int a = 0; a < 4; a++)
#pragma unroll
        for (int b = 0; b < 4; b++)
#pragma unroll
            for (int c = 0; c < 4; c++) acc[a][b][c] = 0.f;

    auto stage = [&](int st, int k0) {
#pragma unroll
        for (int i = 0; i < 2; i++) {
            int s = tid + i * 256;
            int r = s >> 2, c = (s & 3) * 8;
            size_t ga = (size_t)(bm + r) * K + k0 + c;
            cpa16(&sA[(st*2+0)*5120 + r*40 + c], Ah + ga);
            cpa16(&sA[(st*2+1)*5120 + r*40 + c], Al + ga);
            size_t gb = (size_t)(bn + r) * K + k0 + c;
            cpa16(&sB[(st*2+0)*5120 + r*40 + c], Bh + gb);
            cpa16(&sB[(st*2+1)*5120 + r*40 + c], Bl + gb);
        }
        cpcommit();
    };

    const int NT = K / 32;
    stage(0, 0);

    for (int kt = 0; kt < NT; kt++) {
        int st = kt & 1;
        cpwait0();
        __syncthreads();
        if (kt + 1 < NT) stage(st ^ 1, (kt + 1) * 32);

#pragma unroll
        for (int ks = 0; ks < 2; ks++) {
            uint32_t afh[4][4], afl[4][4], bfh[4][2], bfl[4][2];
#pragma unroll
            for (int mf = 0; mf < 4; mf++) {
                int off = (mw*64 + mf*16 + (lane & 15)) * 40 + ks*16 + (lane >> 4) * 8;
                ldsm4(afh[mf], &sA[(st*2+0)*5120 + off]);
                ldsm4(afl[mf], &sA[(st*2+1)*5120 + off]);
            }
#pragma unroll
            for (int nf = 0; nf < 4; nf++) {
                int li = lane & 15;
                int off = (nw*32 + nf*8 + (li & 7)) * 40 + ks*16 + (li >> 3) * 8;
                ldsm2(bfh[nf], &sB[(st*2+0)*5120 + off]);
                ldsm2(bfl[nf], &sB[(st*2+1)*5120 + off]);
            }
#pragma unroll
            for (int mf = 0; mf < 4; mf++)
#pragma unroll
                for (int nf = 0; nf < 4; nf++) {
                    mma16816(acc[mf][nf], afh[mf], bfh[nf]);
                    mma16816(acc[mf][nf], afh[mf], bfl[nf]);
                    mma16816(acc[mf][nf], afl[mf], bfh[nf]);
                }
        }
        __syncthreads();
    }

#pragma unroll
    for (int mf = 0; mf < 4; mf++)
#pragma unroll
        for (int nf = 0; nf < 4; nf++)
#pragma unroll
            for (int c = 0; c < 2; c++) {
                int row = bm + mw*64 + mf*16 + (lane >> 2) + c*8;
                int col = bn + nw*32 + nf*8  + 2*(lane & 3);
                float v0 = acc[mf][nf][2*c+0];
                float v1 = acc[mf][nf][2*c+1];
                if (bias) { v0 += bias[col]; v1 += bias[col+1]; }
                if (Cf) *(float2*)&Cf[(size_t)row * N + col] = make_float2(v0, v1);
                if (Ch) {
                    uint32_t ph, pl;
                    split_pack2(v0, v1, ph, pl);
                    *(uint32_t*)&Ch[(size_t)row * N + col] = ph;
                    *(uint32_t*)&Cl[(size_t)row * N + col] = pl;
                }
            }
}

// ---------------- one-pass attention, 2 CTAs/SM ----------------
// grid (SEQ/128, B*H), 256 threads = 8 warps, each warp owns 16 query rows.
#define KBUF 4608   // 64*72 elements per K/V buffer
__global__ __launch_bounds__(256, 2)
void attn_one(const bf16* __restrict__ qh, const bf16* __restrict__ ql,
              const int* __restrict__ mask,
              float* __restrict__ attn,
              bf16* __restrict__ ctxh, bf16* __restrict__ ctxl)
{
    char* sm = dynsm;
    bf16*  sQh  = (bf16*)sm;                    // 128*72
    bf16*  sQl  = (bf16*)(sm + 18432);
    bf16*  sKb  = (bf16*)(sm + 36864);          // [2 st][2 hl][64*72]
    bf16*  sVb  = (bf16*)(sm + 73728);
    int*   smask = (int*)(sm + 110592);         // [2][64]
    float* lrec  = (float*)(sm + 111104);       // [128]

    const int tid = threadIdx.x, lane = tid & 31, w = tid >> 5;
    const int q0 = blockIdx.x * QT;
    const int bh = blockIdx.y, b = bh >> 4, h = bh & 15;
    const size_t RS = 3 * DMODEL;

    // stage Q
    for (int s = tid; s < 1024; s += 256) {
        int r = s >> 3, c = (s & 7) * 8;
        size_t g = (size_t)(b*SEQ + q0 + r) * RS + h*DHEAD + c;
        cpa16(&sQh[r*72 + c], qh + g);
        cpa16(&sQl[r*72 + c], ql + g);
    }
    cpcommit();

    auto stageKV = [&](int st, int kt) {
        int k0 = kt * 64;
        if (tid < 64) smask[st*64 + tid] = mask[b*SEQ + k0 + tid];
        for (int s = tid; s < 512; s += 256) {
            int r = s >> 3, c = (s & 7) * 8;
            size_t gk = (size_t)(b*SEQ + k0 + r) * RS + DMODEL + h*DHEAD + c;
            size_t gv = gk + DMODEL;
            cpa16(&sKb[(st*2+0)*KBUF + r*72 + c], qh + gk);
            cpa16(&sKb[(st*2+1)*KBUF + r*72 + c], ql + gk);
            cpa16(&sVb[(st*2+0)*KBUF + r*72 + c], qh + gv);
            cpa16(&sVb[(st*2+1)*KBUF + r*72 + c], ql + gv);
        }
        cpcommit();
    };

    stageKV(0, 0);
    cpwait0();
    __syncthreads();

    float oacc[8][4];
#pragma unroll
    for (int nf = 0; nf < 8; nf++)
#pragma unroll
        for (int c = 0; c < 4; c++) oacc[nf][c] = 0.f;
    float rs0 = 0.f, rs1 = 0.f;

    const int rlo = lane >> 2, qq = lane & 3;
    const int g8 = lane >> 3;
    const size_t abase = ((size_t)bh * SEQ + q0) * SEQ;

    for (int kt = 0; kt < 16; kt++) {
        int st = kt & 1;
        if (kt) { cpwait0(); __syncthreads(); }
        if (kt + 1 < 16) stageKV(st ^ 1, kt + 1);

        // ---- S = Q K^T (per-warp m16 x n64), minimal transients ----
        float sacc[8][4];
#pragma unroll
        for (int nf = 0; nf < 8; nf++)
#pragma unroll
            for (int c = 0; c < 4; c++) sacc[nf][c] = 0.f;

#pragma unroll
        for (int ks = 0; ks < 4; ks++) {
            uint32_t q4h[4], q4l[4];
            int qoff = (w*16 + (lane & 15)) * 72 + ks*16 + (lane >> 4) * 8;
            ldsm4(q4h, &sQh[qoff]);
            ldsm4(q4l, &sQl[qoff]);
#pragma unroll
            for (int p = 0; p < 4; p++) {
                int off = (p*16 + (g8 & 1)*8 + (lane & 7)) * 72 + ks*16 + (g8 >> 1) * 8;
                uint32_t r4[4], s4[4];
                ldsm4(r4, &sKb[(st*2+0)*KBUF + off]);
                ldsm4(s4, &sKb[(st*2+1)*KBUF + off]);
                uint32_t b0[2] = {r4[0], r4[2]}, b1[2] = {r4[1], r4[3]};
                uint32_t c0[2] = {s4[0], s4[2]}, c1[2] = {s4[1], s4[3]};
                mma16816(sacc[2*p],   q4h, b0);
                mma16816(sacc[2*p],   q4h, c0);
                mma16816(sacc[2*p],   q4l, b0);
                mma16816(sacc[2*p+1], q4h, b1);
                mma16816(sacc[2*p+1], q4h, c1);
                mma16816(sacc[2*p+1], q4l, b1);
            }
        }

        // ---- exp (poly), mask, store unnormalized p in place ----
#pragma unroll
        for (int nf = 0; nf < 8; nf++) {
            int c0i = nf*8 + 2*qq;
            int m0 = smask[st*64 + c0i];
            int m1 = smask[st*64 + c0i + 1];
            float e0 = m0 ? fexp2p(sacc[nf][0] * Y_SCALE) : 0.f;
            float e1 = m1 ? fexp2p(sacc[nf][1] * Y_SCALE) : 0.f;
            float e2 = m0 ? fexp2p(sacc[nf][2] * Y_SCALE) : 0.f;
            float e3 = m1 ? fexp2p(sacc[nf][3] * Y_SCALE) : 0.f;
            sacc[nf][0] = e0; sacc[nf][1] = e1; sacc[nf][2] = e2; sacc[nf][3] = e3;
            rs0 += e0 + e1;
            rs1 += e2 + e3;
            size_t a0 = abase + (size_t)(w*16 + rlo) * SEQ + kt*64 + c0i;
            *(float2*)&attn[a0]           = make_float2(e0, e1);
            *(float2*)&attn[a0 + 8*SEQ]   = make_float2(e2, e3);
        }

        // ---- O += P @ V (a-frags built per pk, V loaded per p) ----
#pragma unroll
        for (int pk = 0; pk < 4; pk++) {
            uint32_t ah[4], al[4];
            split_pack2(sacc[2*pk][0],   sacc[2*pk][1],   ah[0], al[0]);
            split_pack2(sacc[2*pk][2],   sacc[2*pk][3],   ah[1], al[1]);
            split_pack2(sacc[2*pk+1][0], sacc[2*pk+1][1], ah[2], al[2]);
            split_pack2(sacc[2*pk+1][2], sacc[2*pk+1][3], ah[3], al[3]);
#pragma unroll
            for (int p = 0; p < 4; p++) {
                int off = (pk*16 + (g8 & 1)*8 + (lane & 7)) * 72 + (2*p + (g8 >> 1)) * 8;
                uint32_t r4[4], s4[4];
                ldsm4t(r4, &sVb[(st*2+0)*KBUF + off]);
                ldsm4t(s4, &sVb[(st*2+1)*KBUF + off]);
                uint32_t v0[2] = {r4[0], r4[1]}, v1[2] = {r4[2], r4[3]};
                uint32_t u0[2] = {s4[0], s4[1]}, u1[2] = {s4[2], s4[3]};
                mma16816(oacc[2*p],   ah, v0);
                mma16816(oacc[2*p],   ah, u0);
                mma16816(oacc[2*p],   al, v0);
                mma16816(oacc[2*p+1], ah, v1);
                mma16816(oacc[2*p+1], ah, u1);
                mma16816(oacc[2*p+1], al, v1);
            }
        }
    }

    // ---- finalize: l, ctx, normalize epilogue ----
    rs0 += __shfl_xor_sync(0xffffffffu, rs0, 1);
    rs0 += __shfl_xor_sync(0xffffffffu, rs0, 2);
    rs1 += __shfl_xor_sync(0xffffffffu, rs1, 1);
    rs1 += __shfl_xor_sync(0xffffffffu, rs1, 2);
    float ri0 = 1.f / rs0, ri1 = 1.f / rs1;
    if ((lane & 3) == 0) {
        lrec[w*16 + rlo]     = ri0;
        lrec[w*16 + rlo + 8] = ri1;
    }

    const size_t row0 = (size_t)(b*SEQ + q0 + w*16 + rlo);
#pragma unroll
    for (int nf = 0; nf < 8; nf++) {
        int col = h*DHEAD + nf*8 + 2*qq;
        uint32_t ph, pl;
        split_pack2(oacc[nf][0] * ri0, oacc[nf][1] * ri0, ph, pl);
        *(uint32_t*)&ctxh[row0*DMODEL + col] = ph;
        *(uint32_t*)&ctxl[row0*DMODEL + col] = pl;
        split_pack2(oacc[nf][2] * ri1, oacc[nf][3] * ri1, ph, pl);
        *(uint32_t*)&ctxh[(row0+8)*DMODEL + col] = ph;
        *(uint32_t*)&ctxl[(row0+8)*DMODEL + col] = pl;
    }

    __syncthreads();   // lrec visible + all attn stores in-block visible

    // normalize this block's attn region (L2-hot re-read)
    for (int s = tid; s < QT * 256; s += 256) {
        int r = s >> 8, c = (s & 255) * 4;
        float sc = lrec[r];
        float4* p = (float4*)(attn + abase + (size_t)r * SEQ + c);
        float4 v = *p;
        v.x *= sc; v.y *= sc; v.z *= sc; v.w *= sc;
        *p = v;
    }
}

// ---------------- launcher ----------------
extern "C" void kernel_launch(void* const* d_in, const int* in_sizes, int n_in,
                              void* d_out, int out_size)
{
    const float* x     = (const float*)d_in[0];
    const int*   mask  = (const int*)d_in[1];
    const float* w_qkv = (const float*)d_in[2];
    const float* w_out = (const float*)d_in[3];
    const float* b_out = (const float*)d_in[4];

    float* out  = (float*)d_out;
    float* attn = out + MROWS * DMODEL;

    bf16 *xh, *xl, *wqh, *wql, *woh, *wol, *qkvh, *qkvl, *ctxh, *ctxl;
    cudaGetSymbolAddress((void**)&xh,  g_xh);  cudaGetSymbolAddress((void**)&xl,  g_xl);
    cudaGetSymbolAddress((void**)&wqh, g_wqt_h); cudaGetSymbolAddress((void**)&wql, g_wqt_l);
    cudaGetSymbolAddress((void**)&woh, g_wot_h); cudaGetSymbolAddress((void**)&wol, g_wot_l);
    cudaGetSymbolAddress((void**)&qkvh, g_qkvh); cudaGetSymbolAddress((void**)&qkvl, g_qkvl);
    cudaGetSymbolAddress((void**)&ctxh, g_ctxh); cudaGetSymbolAddress((void**)&ctxl, g_ctxl);

    cudaFuncSetAttribute(mma_gemm, cudaFuncAttributeMaxDynamicSharedMemorySize, 81920);
    cudaFuncSetAttribute(attn_one, cudaFuncAttributeMaxDynamicSharedMemorySize, 111616);

    {
        int n4 = (int)(MROWS * DMODEL / 4);
        split_kernel<<<(n4 + 255) / 256, 256>>>(x, xh, xl, n4);
    }
    transpose_split<<<dim3(3*DMODEL/32, DMODEL/32), dim3(32,8)>>>(w_qkv, wqh, wql, DMODEL, 3*DMODEL);
    transpose_split<<<dim3(DMODEL/32,   DMODEL/32), dim3(32,8)>>>(w_out, woh, wol, DMODEL, DMODEL);

    mma_gemm<<<dim3(3*DMODEL/128, (int)(MROWS/128)), 256, 81920>>>(
        xh, xl, wqh, wql, nullptr, qkvh, qkvl, nullptr,
        (int)MROWS, 3*DMODEL, DMODEL);

    attn_one<<<dim3(SEQ/QT, BDIM*NHEAD), 256, 111616>>>(
        qkvh, qkvl, mask, attn, ctxh, ctxl);

    mma_gemm<<<dim3(DMODEL/128, (int)(MROWS/128)), 256, 81920>>>(
        ctxh, ctxl, woh, wol, out, nullptr, nullptr, b_out,
        (int)MROWS, DMODEL, DMODEL);
}

// round 8
// speedup vs baseline: 2.5130x; 1.0299x over previous
#include <cuda_runtime.h>
#include <cuda_bf16.h>
#include <math.h>
#include <stdint.h>

#define BDIM   8
#define SEQ    1024
#define DMODEL 1024
#define NHEAD  16
#define DHEAD  64
#define QT     128

typedef __nv_bfloat16  bf16;
typedef __nv_bfloat162 bf162;

#define MROWS ((size_t)BDIM * SEQ)

// single dynamic-smem symbol shared by all kernels
extern __shared__ __align__(16) char dynsm[];

// ---- scratch (device globals; no runtime alloc) ----
__device__ bf16 g_xh[MROWS * DMODEL],        g_xl[MROWS * DMODEL];
__device__ bf16 g_wqt_h[(size_t)3*DMODEL*DMODEL], g_wqt_l[(size_t)3*DMODEL*DMODEL];
__device__ bf16 g_wot_h[(size_t)DMODEL*DMODEL],   g_wot_l[(size_t)DMODEL*DMODEL];
__device__ bf16 g_qkvh[MROWS * 3*DMODEL],    g_qkvl[MROWS * 3*DMODEL];
__device__ bf16 g_ctxh[MROWS * DMODEL],      g_ctxl[MROWS * DMODEL];

// ---------------- helpers ----------------
__device__ __forceinline__ uint32_t sptr(const void* p) {
    return (uint32_t)__cvta_generic_to_shared(p);
}
__device__ __forceinline__ void cpa16(void* s, const void* g) {
    asm volatile("cp.async.cg.shared.global [%0], [%1], 16;\n" :: "r"(sptr(s)), "l"(g));
}
__device__ __forceinline__ void cpa16s(uint32_t s, const void* g) {
    asm volatile("cp.async.cg.shared.global [%0], [%1], 16;\n" :: "r"(s), "l"(g));
}
__device__ __forceinline__ void cpcommit() { asm volatile("cp.async.commit_group;\n"); }
__device__ __forceinline__ void cpwait0()  { asm volatile("cp.async.wait_group 0;\n"); }
__device__ __forceinline__ void cpwait1()  { asm volatile("cp.async.wait_group 1;\n"); }

__device__ __forceinline__ void ldsm4(uint32_t* r, const void* p) {
    asm volatile("ldmatrix.sync.aligned.m8n8.x4.shared.b16 {%0,%1,%2,%3}, [%4];\n"
        : "=r"(r[0]), "=r"(r[1]), "=r"(r[2]), "=r"(r[3]) : "r"(sptr(p)));
}
__device__ __forceinline__ void ldsm4s(uint32_t* r, uint32_t a) {
    asm volatile("ldmatrix.sync.aligned.m8n8.x4.shared.b16 {%0,%1,%2,%3}, [%4];\n"
        : "=r"(r[0]), "=r"(r[1]), "=r"(r[2]), "=r"(r[3]) : "r"(a));
}
__device__ __forceinline__ void ldsm4t(uint32_t* r, const void* p) {
    asm volatile("ldmatrix.sync.aligned.m8n8.x4.trans.shared.b16 {%0,%1,%2,%3}, [%4];\n"
        : "=r"(r[0]), "=r"(r[1]), "=r"(r[2]), "=r"(r[3]) : "r"(sptr(p)));
}
__device__ __forceinline__ void ldsm2s(uint32_t* r, uint32_t a) {
    asm volatile("ldmatrix.sync.aligned.m8n8.x2.shared.b16 {%0,%1}, [%2];\n"
        : "=r"(r[0]), "=r"(r[1]) : "r"(a));
}
__device__ __forceinline__ void mma16816(float* c, const uint32_t* a, const uint32_t* b) {
    asm volatile("mma.sync.aligned.m16n8k16.row.col.f32.bf16.bf16.f32 "
        "{%0,%1,%2,%3}, {%4,%5,%6,%7}, {%8,%9}, {%0,%1,%2,%3};\n"
        : "+f"(c[0]), "+f"(c[1]), "+f"(c[2]), "+f"(c[3])
        : "r"(a[0]), "r"(a[1]), "r"(a[2]), "r"(a[3]), "r"(b[0]), "r"(b[1]));
}
__device__ __forceinline__ void split1(float v, bf16& h, bf16& l) {
    h = __float2bfloat16_rn(v);
    l = __float2bfloat16_rn(v - __bfloat162float(h));
}
__device__ __forceinline__ uint32_t pack2(bf16 lo, bf16 hi) {
    return (uint32_t)__bfloat16_as_ushort(lo) | ((uint32_t)__bfloat16_as_ushort(hi) << 16);
}
__device__ __forceinline__ void split_pack2(float v0, float v1, uint32_t& ph, uint32_t& pl) {
    bf16 h0,l0,h1,l1;
    split1(v0,h0,l0); split1(v1,h1,l1);
    ph = pack2(h0,h1);
    pl = pack2(l0,l1);
}
// SW64 swizzle: XOR bits[5:4] with bits[8:7] (64B rows)
__device__ __forceinline__ uint32_t sw64(uint32_t off) {
    return off ^ ((off >> 3) & 0x30);
}
// 2^y via magic rounding + degree-5 poly (FMA pipe only, no MUFU). |y| < 30.
__device__ __forceinline__ float fexp2p(float y) {
    float t = y + 12582912.f;
    float n = t - 12582912.f;
    float f = y - n;
    float p = 0.00133335581f;
    p = fmaf(p, f, 0.00961812911f);
    p = fmaf(p, f, 0.05550410866f);
    p = fmaf(p, f, 0.24022650696f);
    p = fmaf(p, f, 0.69314718056f);
    p = fmaf(p, f, 1.0f);
    int e = (__float_as_int(t) - 0x4B400000 + 127) << 23;
    return __int_as_float(e) * p;
}
#define Y_SCALE 0.18033688011112042f   // 0.125 * log2(e)

// ---------------- converters ----------------
__global__ void split_kernel(const float* __restrict__ in,
                             bf16* __restrict__ oh, bf16* __restrict__ ol, int n4)
{
    int i = blockIdx.x * blockDim.x + threadIdx.x;
    if (i >= n4) return;
    float4 v = ((const float4*)in)[i];
    uint32_t ph0, pl0, ph1, pl1;
    split_pack2(v.x, v.y, ph0, pl0);
    split_pack2(v.z, v.w, ph1, pl1);
    ((uint32_t*)oh)[2*i]   = ph0;
    ((uint32_t*)oh)[2*i+1] = ph1;
    ((uint32_t*)ol)[2*i]   = pl0;
    ((uint32_t*)ol)[2*i+1] = pl1;
}

__global__ void transpose_split(const float* __restrict__ in,
                                bf16* __restrict__ oh, bf16* __restrict__ ol,
                                int K, int N)
{
    __shared__ float t[32][33];
    int k0 = blockIdx.y * 32, n0 = blockIdx.x * 32;
    int tx = threadIdx.x, ty = threadIdx.y;
#pragma unroll
    for (int i = 0; i < 4; i++)
        t[ty + 8*i][tx] = in[(size_t)(k0 + ty + 8*i) * N + n0 + tx];
    __syncthreads();
#pragma unroll
    for (int i = 0; i < 4; i++) {
        float v = t[tx][ty + 8*i];
        bf16 h, l; split1(v, h, l);
        size_t o = (size_t)(n0 + ty + 8*i) * K + k0 + tx;
        oh[o] = h; ol[o] = l;
    }
}

// ---------------- GEMM (bf16 split, 3-term), 3-stage pipeline, 2 CTAs/SM ----
// Per stage (BK=32): Ah,Al,Bh,Bl buffers, each 128x32 bf16 = 8KB, SW64 swizzled.
#define GSTG 32768
__global__ __launch_bounds__(256, 2)
void mma_gemm(const bf16* __restrict__ Ah, const bf16* __restrict__ Al,
              const bf16* __restrict__ Bh, const bf16* __restrict__ Bl,
              float* __restrict__ Cf, bf16* __restrict__ Ch, bf16* __restrict__ Cl,
              const float* __restrict__ bias, int M, int N, int K)
{
    const uint32_t smbase = (sptr(dynsm) + 1023u) & ~1023u;

    const int tid  = threadIdx.x;
    const int lane = tid & 31, wid = tid >> 5;
    const int mw = wid >> 2, nw = wid & 3;
    const int bm = blockIdx.y * 128, bn = blockIdx.x * 128;

    float acc[4][4][4];
#pragma unroll
    for (int a = 0; a < 4; a++)
#pragma unroll
        for (int b = 0; b < 4; b++)
#pragma unroll
            for (int c = 0; c < 4; c++) acc[a][b][c] = 0.f;

    auto stage = [&](int st, int kc) {
        const int k0 = kc * 32;
        const uint32_t sb = smbase + st * GSTG;
#pragma unroll
        for (int i = 0; i < 2; i++) {
            int s = tid + i * 256;
            int r = s >> 2, c = (s & 3) * 8;
            uint32_t off = sw64((uint32_t)(r * 64 + c * 2));
            size_t ga = (size_t)(bm + r) * K + k0 + c;
            size_t gb = (size_t)(bn + r) * K + k0 + c;
            cpa16s(sb + off,         Ah + ga);
            cpa16s(sb +  8192 + off, Al + ga);
            cpa16s(sb + 16384 + off, Bh + gb);
            cpa16s(sb + 24576 + off, Bl + gb);
        }
        cpcommit();
    };

    const int NT = K / 32;
    stage(0, 0);
    stage(1, 1);

    for (int kt = 0; kt < NT; kt++) {
        const uint32_t sb = smbase + (kt % 3) * GSTG;
        if (kt + 1 < NT) cpwait1(); else cpwait0();
        __syncthreads();
        if (kt + 2 < NT) stage((kt + 2) % 3, kt + 2);

#pragma unroll
        for (int ks = 0; ks < 2; ks++) {
            uint32_t afh[4][4], afl[4][4], bfh[4][2], bfl[4][2];
#pragma unroll
            for (int mf = 0; mf < 4; mf++) {
                int row = mw*64 + mf*16 + (lane & 15);
                int col = ks*16 + (lane >> 4) * 8;
                uint32_t off = sw64((uint32_t)(row * 64 + col * 2));
                ldsm4s(afh[mf], sb + off);
                ldsm4s(afl[mf], sb + 8192 + off);
            }
#pragma unroll
            for (int nf = 0; nf < 4; nf++) {
                int li = lane & 15;
                int row = nw*32 + nf*8 + (li & 7);
                int col = ks*16 + (li >> 3) * 8;
                uint32_t off = sw64((uint32_t)(row * 64 + col * 2));
                ldsm2s(bfh[nf], sb + 16384 + off);
                ldsm2s(bfl[nf], sb + 24576 + off);
            }
#pragma unroll
            for (int mf = 0; mf < 4; mf++)
#pragma unroll
                for (int nf = 0; nf < 4; nf++) {
                    mma16816(acc[mf][nf], afh[mf], bfh[nf]);
                    mma16816(acc[mf][nf], afh[mf], bfl[nf]);
                    mma16816(acc[mf][nf], afl[mf], bfh[nf]);
                }
        }
    }

#pragma unroll
    for (int mf = 0; mf < 4; mf++)
#pragma unroll
        for (int nf = 0; nf < 4; nf++)
#pragma unroll
            for (int c = 0; c < 2; c++) {
                int row = bm + mw*64 + mf*16 + (lane >> 2) + c*8;
                int col = bn + nw*32 + nf*8  + 2*(lane & 3);
                float v0 = acc[mf][nf][2*c+0];
                float v1 = acc[mf][nf][2*c+1];
                if (bias) { v0 += bias[col]; v1 += bias[col+1]; }
                if (Cf) *(float2*)&Cf[(size_t)row * N + col] = make_float2(v0, v1);
                if (Ch) {
                    uint32_t ph, pl;
                    split_pack2(v0, v1, ph, pl);
                    *(uint32_t*)&Ch[(size_t)row * N + col] = ph;
                    *(uint32_t*)&Cl[(size_t)row * N + col] = pl;
                }
            }
}

// ---------------- one-pass attention, 2 CTAs/SM (unchanged from R6) ----------
#define KBUF 4608   // 64*72 elements per K/V buffer
__global__ __launch_bounds__(256, 2)
void attn_one(const bf16* __restrict__ qh, const bf16* __restrict__ ql,
              const int* __restrict__ mask,
              float* __restrict__ attn,
              bf16* __restrict__ ctxh, bf16* __restrict__ ctxl)
{
    char* sm = dynsm;
    bf16*  sQh  = (bf16*)sm;                    // 128*72
    bf16*  sQl  = (bf16*)(sm + 18432);
    bf16*  sKb  = (bf16*)(sm + 36864);          // [2 st][2 hl][64*72]
    bf16*  sVb  = (bf16*)(sm + 73728);
    int*   smask = (int*)(sm + 110592);         // [2][64]
    float* lrec  = (float*)(sm + 111104);       // [128]

    const int tid = threadIdx.x, lane = tid & 31, w = tid >> 5;
    const int q0 = blockIdx.x * QT;
    const int bh = blockIdx.y, b = bh >> 4, h = bh & 15;
    const size_t RS = 3 * DMODEL;

    for (int s = tid; s < 1024; s += 256) {
        int r = s >> 3, c = (s & 7) * 8;
        size_t g = (size_t)(b*SEQ + q0 + r) * RS + h*DHEAD + c;
        cpa16(&sQh[r*72 + c], qh + g);
        cpa16(&sQl[r*72 + c], ql + g);
    }
    cpcommit();

    auto stageKV = [&](int st, int kt) {
        int k0 = kt * 64;
        if (tid < 64) smask[st*64 + tid] = mask[b*SEQ + k0 + tid];
        for (int s = tid; s < 512; s += 256) {
            int r = s >> 3, c = (s & 7) * 8;
            size_t gk = (size_t)(b*SEQ + k0 + r) * RS + DMODEL + h*DHEAD + c;
            size_t gv = gk + DMODEL;
            cpa16(&sKb[(st*2+0)*KBUF + r*72 + c], qh + gk);
            cpa16(&sKb[(st*2+1)*KBUF + r*72 + c], ql + gk);
            cpa16(&sVb[(st*2+0)*KBUF + r*72 + c], qh + gv);
            cpa16(&sVb[(st*2+1)*KBUF + r*72 + c], ql + gv);
        }
        cpcommit();
    };

    stageKV(0, 0);
    cpwait0();
    __syncthreads();

    float oacc[8][4];
#pragma unroll
    for (int nf = 0; nf < 8; nf++)
#pragma unroll
        for (int c = 0; c < 4; c++) oacc[nf][c] = 0.f;
    float rs0 = 0.f, rs1 = 0.f;

    const int rlo = lane >> 2, qq = lane & 3;
    const int g8 = lane >> 3;
    const size_t abase = ((size_t)bh * SEQ + q0) * SEQ;

    for (int kt = 0; kt < 16; kt++) {
        int st = kt & 1;
        if (kt) { cpwait0(); __syncthreads(); }
        if (kt + 1 < 16) stageKV(st ^ 1, kt + 1);

        float sacc[8][4];
#pragma unroll
        for (int nf = 0; nf < 8; nf++)
#pragma unroll
            for (int c = 0; c < 4; c++) sacc[nf][c] = 0.f;

#pragma unroll
        for (int ks = 0; ks < 4; ks++) {
            uint32_t q4h[4], q4l[4];
            int qoff = (w*16 + (lane & 15)) * 72 + ks*16 + (lane >> 4) * 8;
            ldsm4(q4h, &sQh[qoff]);
            ldsm4(q4l, &sQl[qoff]);
#pragma unroll
            for (int p = 0; p < 4; p++) {
                int off = (p*16 + (g8 & 1)*8 + (lane & 7)) * 72 + ks*16 + (g8 >> 1) * 8;
                uint32_t r4[4], s4[4];
                ldsm4(r4, &sKb[(st*2+0)*KBUF + off]);
                ldsm4(s4, &sKb[(st*2+1)*KBUF + off]);
                uint32_t b0[2] = {r4[0], r4[2]}, b1[2] = {r4[1], r4[3]};
                uint32_t c0[2] = {s4[0], s4[2]}, c1[2] = {s4[1], s4[3]};
                mma16816(sacc[2*p],   q4h, b0);
                mma16816(sacc[2*p],   q4h, c0);
                mma16816(sacc[2*p],   q4l, b0);
                mma16816(sacc[2*p+1], q4h, b1);
                mma16816(sacc[2*p+1], q4h, c1);
                mma16816(sacc[2*p+1], q4l, b1);
            }
        }

#pragma unroll
        for (int nf = 0; nf < 8; nf++) {
            int c0i = nf*8 + 2*qq;
            int m0 = smask[st*64 + c0i];
            int m1 = smask[st*64 + c0i + 1];
            float e0 = m0 ? fexp2p(sacc[nf][0] * Y_SCALE) : 0.f;
            float e1 = m1 ? fexp2p(sacc[nf][1] * Y_SCALE) : 0.f;
            float e2 = m0 ? fexp2p(sacc[nf][2] * Y_SCALE) : 0.f;
            float e3 = m1 ? fexp2p(sacc[nf][3] * Y_SCALE) : 0.f;
            sacc[nf][0] = e0; sacc[nf][1] = e1; sacc[nf][2] = e2; sacc[nf][3] = e3;
            rs0 += e0 + e1;
            rs1 += e2 + e3;
            size_t a0 = abase + (size_t)(w*16 + rlo) * SEQ + kt*64 + c0i;
            *(float2*)&attn[a0]           = make_float2(e0, e1);
            *(float2*)&attn[a0 + 8*SEQ]   = make_float2(e2, e3);
        }

#pragma unroll
        for (int pk = 0; pk < 4; pk++) {
            uint32_t ah[4], al[4];
            split_pack2(sacc[2*pk][0],   sacc[2*pk][1],   ah[0], al[0]);
            split_pack2(sacc[2*pk][2],   sacc[2*pk][3],   ah[1], al[1]);
            split_pack2(sacc[2*pk+1][0], sacc[2*pk+1][1], ah[2], al[2]);
            split_pack2(sacc[2*pk+1][2], sacc[2*pk+1][3], ah[3], al[3]);
#pragma unroll
            for (int p = 0; p < 4; p++) {
                int off = (pk*16 + (g8 & 1)*8 + (lane & 7)) * 72 + (2*p + (g8 >> 1)) * 8;
                uint32_t r4[4], s4[4];
                ldsm4t(r4, &sVb[(st*2+0)*KBUF + off]);
                ldsm4t(s4, &sVb[(st*2+1)*KBUF + off]);
                uint32_t v0[2] = {r4[0], r4[1]}, v1[2] = {r4[2], r4[3]};
                uint32_t u0[2] = {s4[0], s4[1]}, u1[2] = {s4[2], s4[3]};
                mma16816(oacc[2*p],   ah, v0);
                mma16816(oacc[2*p],   ah, u0);
                mma16816(oacc[2*p],   al, v0);
                mma16816(oacc[2*p+1], ah, v1);
                mma16816(oacc[2*p+1], ah, u1);
                mma16816(oacc[2*p+1], al, v1);
            }
        }
    }

    rs0 += __shfl_xor_sync(0xffffffffu, rs0, 1);
    rs0 += __shfl_xor_sync(0xffffffffu, rs0, 2);
    rs1 += __shfl_xor_sync(0xffffffffu, rs1, 1);
    rs1 += __shfl_xor_sync(0xffffffffu, rs1, 2);
    float ri0 = 1.f / rs0, ri1 = 1.f / rs1;
    if ((lane & 3) == 0) {
        lrec[w*16 + rlo]     = ri0;
        lrec[w*16 + rlo + 8] = ri1;
    }

    const size_t row0 = (size_t)(b*SEQ + q0 + w*16 + rlo);
#pragma unroll
    for (int nf = 0; nf < 8; nf++) {
        int col = h*DHEAD + nf*8 + 2*qq;
        uint32_t hp, lp;
        split_pack2(oacc[nf][0] * ri0, oacc[nf][1] * ri0, hp, lp);
        *(uint32_t*)&ctxh[row0*DMODEL + col] = hp;
        *(uint32_t*)&ctxl[row0*DMODEL + col] = lp;
        split_pack2(oacc[nf][2] * ri1, oacc[nf][3] * ri1, hp, lp);
        *(uint32_t*)&ctxh[(row0+8)*DMODEL + col] = hp;
        *(uint32_t*)&ctxl[(row0+8)*DMODEL + col] = lp;
    }

    __syncthreads();

    for (int s = tid; s < QT * 256; s += 256) {
        int r = s >> 8, c = (s & 255) * 4;
        float sc = lrec[r];
        float4* p = (float4*)(attn + abase + (size_t)r * SEQ + c);
        float4 v = *p;
        v.x *= sc; v.y *= sc; v.z *= sc; v.w *= sc;
        *p = v;
    }
}

// ---------------- launcher ----------------
extern "C" void kernel_launch(void* const* d_in, const int* in_sizes, int n_in,
                              void* d_out, int out_size)
{
    const float* x     = (const float*)d_in[0];
    const int*   mask  = (const int*)d_in[1];
    const float* w_qkv = (const float*)d_in[2];
    const float* w_out = (const float*)d_in[3];
    const float* b_out = (const float*)d_in[4];

    float* out  = (float*)d_out;
    float* attn = out + MROWS * DMODEL;

    bf16 *xh, *xl, *wqh, *wql, *woh, *wol, *qkvh, *qkvl, *ctxh, *ctxl;
    cudaGetSymbolAddress((void**)&xh,  g_xh);  cudaGetSymbolAddress((void**)&xl,  g_xl);
    cudaGetSymbolAddress((void**)&wqh, g_wqt_h); cudaGetSymbolAddress((void**)&wql, g_wqt_l);
    cudaGetSymbolAddress((void**)&woh, g_wot_h); cudaGetSymbolAddress((void**)&wol, g_wot_l);
    cudaGetSymbolAddress((void**)&qkvh, g_qkvh); cudaGetSymbolAddress((void**)&qkvl, g_qkvl);
    cudaGetSymbolAddress((void**)&ctxh, g_ctxh); cudaGetSymbolAddress((void**)&ctxl, g_ctxl);

    cudaFuncSetAttribute(mma_gemm, cudaFuncAttributeMaxDynamicSharedMemorySize, 99328);
    cudaFuncSetAttribute(attn_one, cudaFuncAttributeMaxDynamicSharedMemorySize, 111616);

    {
        int n4 = (int)(MROWS * DMODEL / 4);
        split_kernel<<<(n4 + 255) / 256, 256>>>(x, xh, xl, n4);
    }
    transpose_split<<<dim3(3*DMODEL/32, DMODEL/32), dim3(32,8)>>>(w_qkv, wqh, wql, DMODEL, 3*DMODEL);
    transpose_split<<<dim3(DMODEL/32,   DMODEL/32), dim3(32,8)>>>(w_out, woh, wol, DMODEL, DMODEL);

    mma_gemm<<<dim3(3*DMODEL/128, (int)(MROWS/128)), 256, 99328>>>(
        xh, xl, wqh, wql, nullptr, qkvh, qkvl, nullptr,
        (int)MROWS, 3*DMODEL, DMODEL);

    attn_one<<<dim3(SEQ/QT, BDIM*NHEAD), 256, 111616>>>(
        qkvh, qkvl, mask, attn, ctxh, ctxl);

    mma_gemm<<<dim3(DMODEL/128, (int)(MROWS/128)), 256, 99328>>>(
        ctxh, ctxl, woh, wol, out, nullptr, nullptr, b_out,
        (int)MROWS, DMODEL, DMODEL);
}

// round 9
// speedup vs baseline: 2.5185x; 1.0022x over previous
#include <cuda_runtime.h>
#include <cuda_bf16.h>
#include <math.h>
#include <stdint.h>

#define BDIM   8
#define SEQ    1024
#define DMODEL 1024
#define NHEAD  16
#define DHEAD  64
#define QT     128

typedef __nv_bfloat16  bf16;
typedef __nv_bfloat162 bf162;

#define MROWS ((size_t)BDIM * SEQ)

// single dynamic-smem symbol shared by all kernels
extern __shared__ __align__(16) char dynsm[];

// ---- scratch (device globals; no runtime alloc) ----
__device__ bf16 g_xh[MROWS * DMODEL],        g_xl[MROWS * DMODEL];
__device__ bf16 g_wqt_h[(size_t)3*DMODEL*DMODEL], g_wqt_l[(size_t)3*DMODEL*DMODEL];
__device__ bf16 g_wot_h[(size_t)DMODEL*DMODEL],   g_wot_l[(size_t)DMODEL*DMODEL];
__device__ bf16 g_qkvh[MROWS * 3*DMODEL],    g_qkvl[MROWS * 3*DMODEL];
__device__ bf16 g_ctxh[MROWS * DMODEL],      g_ctxl[MROWS * DMODEL];

// ---------------- helpers ----------------
__device__ __forceinline__ uint32_t sptr(const void* p) {
    return (uint32_t)__cvta_generic_to_shared(p);
}
__device__ __forceinline__ void cpa16(void* s, const void* g) {
    asm volatile("cp.async.cg.shared.global [%0], [%1], 16;\n" :: "r"(sptr(s)), "l"(g));
}
__device__ __forceinline__ void cpa16s(uint32_t s, const void* g) {
    asm volatile("cp.async.cg.shared.global [%0], [%1], 16;\n" :: "r"(s), "l"(g));
}
__device__ __forceinline__ void cpcommit() { asm volatile("cp.async.commit_group;\n"); }
__device__ __forceinline__ void cpwait0()  { asm volatile("cp.async.wait_group 0;\n"); }
__device__ __forceinline__ void cpwait1()  { asm volatile("cp.async.wait_group 1;\n"); }

__device__ __forceinline__ void ldsm4(uint32_t* r, const void* p) {
    asm volatile("ldmatrix.sync.aligned.m8n8.x4.shared.b16 {%0,%1,%2,%3}, [%4];\n"
        : "=r"(r[0]), "=r"(r[1]), "=r"(r[2]), "=r"(r[3]) : "r"(sptr(p)));
}
__device__ __forceinline__ void ldsm4s(uint32_t* r, uint32_t a) {
    asm volatile("ldmatrix.sync.aligned.m8n8.x4.shared.b16 {%0,%1,%2,%3}, [%4];\n"
        : "=r"(r[0]), "=r"(r[1]), "=r"(r[2]), "=r"(r[3]) : "r"(a));
}
__device__ __forceinline__ void ldsm4t(uint32_t* r, const void* p) {
    asm volatile("ldmatrix.sync.aligned.m8n8.x4.trans.shared.b16 {%0,%1,%2,%3}, [%4];\n"
        : "=r"(r[0]), "=r"(r[1]), "=r"(r[2]), "=r"(r[3]) : "r"(sptr(p)));
}
__device__ __forceinline__ void ldsm2s(uint32_t* r, uint32_t a) {
    asm volatile("ldmatrix.sync.aligned.m8n8.x2.shared.b16 {%0,%1}, [%2];\n"
        : "=r"(r[0]), "=r"(r[1]) : "r"(a));
}
__device__ __forceinline__ void mma16816(float* c, const uint32_t* a, const uint32_t* b) {
    asm volatile("mma.sync.aligned.m16n8k16.row.col.f32.bf16.bf16.f32 "
        "{%0,%1,%2,%3}, {%4,%5,%6,%7}, {%8,%9}, {%0,%1,%2,%3};\n"
        : "+f"(c[0]), "+f"(c[1]), "+f"(c[2]), "+f"(c[3])
        : "r"(a[0]), "r"(a[1]), "r"(a[2]), "r"(a[3]), "r"(b[0]), "r"(b[1]));
}
__device__ __forceinline__ void split1(float v, bf16& h, bf16& l) {
    h = __float2bfloat16_rn(v);
    l = __float2bfloat16_rn(v - __bfloat162float(h));
}
__device__ __forceinline__ uint32_t pack2(bf16 lo, bf16 hi) {
    return (uint32_t)__bfloat16_as_ushort(lo) | ((uint32_t)__bfloat16_as_ushort(hi) << 16);
}
__device__ __forceinline__ void split_pack2(float v0, float v1, uint32_t& ph, uint32_t& pl) {
    bf16 h0,l0,h1,l1;
    split1(v0,h0,l0); split1(v1,h1,l1);
    ph = pack2(h0,h1);
    pl = pack2(l0,l1);
}
// SW64 swizzle: XOR bits[5:4] with bits[8:7] (64B rows)
__device__ __forceinline__ uint32_t sw64(uint32_t off) {
    return off ^ ((off >> 3) & 0x30);
}
// 2^y via magic rounding + degree-5 poly (FMA pipe only, no MUFU). |y| < 30.
__device__ __forceinline__ float fexp2p(float y) {
    float t = y + 12582912.f;
    float n = t - 12582912.f;
    float f = y - n;
    float p = 0.00133335581f;
    p = fmaf(p, f, 0.00961812911f);
    p = fmaf(p, f, 0.05550410866f);
    p = fmaf(p, f, 0.24022650696f);
    p = fmaf(p, f, 0.69314718056f);
    p = fmaf(p, f, 1.0f);
    int e = (__float_as_int(t) - 0x4B400000 + 127) << 23;
    return __int_as_float(e) * p;
}
#define Y_SCALE 0.18033688011112042f   // 0.125 * log2(e)

// ---------------- converters ----------------
__global__ void split_kernel(const float* __restrict__ in,
                             bf16* __restrict__ oh, bf16* __restrict__ ol, int n4)
{
    int i = blockIdx.x * blockDim.x + threadIdx.x;
    if (i >= n4) return;
    float4 v = ((const float4*)in)[i];
    uint32_t ph0, pl0, ph1, pl1;
    split_pack2(v.x, v.y, ph0, pl0);
    split_pack2(v.z, v.w, ph1, pl1);
    ((uint32_t*)oh)[2*i]   = ph0;
    ((uint32_t*)oh)[2*i+1] = ph1;
    ((uint32_t*)ol)[2*i]   = pl0;
    ((uint32_t*)ol)[2*i+1] = pl1;
}

__global__ void transpose_split(const float* __restrict__ in,
                                bf16* __restrict__ oh, bf16* __restrict__ ol,
                                int K, int N)
{
    __shared__ float t[32][33];
    int k0 = blockIdx.y * 32, n0 = blockIdx.x * 32;
    int tx = threadIdx.x, ty = threadIdx.y;
#pragma unroll
    for (int i = 0; i < 4; i++)
        t[ty + 8*i][tx] = in[(size_t)(k0 + ty + 8*i) * N + n0 + tx];
    __syncthreads();
#pragma unroll
    for (int i = 0; i < 4; i++) {
        float v = t[tx][ty + 8*i];
        bf16 h, l; split1(v, h, l);
        size_t o = (size_t)(n0 + ty + 8*i) * K + k0 + tx;
        oh[o] = h; ol[o] = l;
    }
}

// ---------------- GEMM (bf16 split, 3-term), 3-stage pipeline, 2 CTAs/SM ----
// Per stage (BK=32): Ah,Al,Bh,Bl buffers, each 128x32 bf16 = 8KB, SW64 swizzled.
// MMA block is term-ordered: 3 passes over all 16 accumulators -> no acc RAW chains.
#define GSTG 32768
__global__ __launch_bounds__(256, 2)
void mma_gemm(const bf16* __restrict__ Ah, const bf16* __restrict__ Al,
              const bf16* __restrict__ Bh, const bf16* __restrict__ Bl,
              float* __restrict__ Cf, bf16* __restrict__ Ch, bf16* __restrict__ Cl,
              const float* __restrict__ bias, int M, int N, int K)
{
    const uint32_t smbase = (sptr(dynsm) + 1023u) & ~1023u;

    const int tid  = threadIdx.x;
    const int lane = tid & 31, wid = tid >> 5;
    const int mw = wid >> 2, nw = wid & 3;
    const int bm = blockIdx.y * 128, bn = blockIdx.x * 128;

    float acc[4][4][4];
#pragma unroll
    for (int a = 0; a < 4; a++)
#pragma unroll
        for (int b = 0; b < 4; b++)
#pragma unroll
            for (int c = 0; c < 4; c++) acc[a][b][c] = 0.f;

    auto stage = [&](int st, int kc) {
        const int k0 = kc * 32;
        const uint32_t sb = smbase + st * GSTG;
#pragma unroll
        for (int i = 0; i < 2; i++) {
            int s = tid + i * 256;
            int r = s >> 2, c = (s & 3) * 8;
            uint32_t off = sw64((uint32_t)(r * 64 + c * 2));
            size_t ga = (size_t)(bm + r) * K + k0 + c;
            size_t gb = (size_t)(bn + r) * K + k0 + c;
            cpa16s(sb + off,         Ah + ga);
            cpa16s(sb +  8192 + off, Al + ga);
            cpa16s(sb + 16384 + off, Bh + gb);
            cpa16s(sb + 24576 + off, Bl + gb);
        }
        cpcommit();
    };

    const int NT = K / 32;
    stage(0, 0);
    stage(1, 1);

    for (int kt = 0; kt < NT; kt++) {
        const uint32_t sb = smbase + (kt % 3) * GSTG;
        if (kt + 1 < NT) cpwait1(); else cpwait0();
        __syncthreads();
        if (kt + 2 < NT) stage((kt + 2) % 3, kt + 2);

#pragma unroll
        for (int ks = 0; ks < 2; ks++) {
            uint32_t afh[4][4], afl[4][4], bfh[4][2], bfl[4][2];
#pragma unroll
            for (int mf = 0; mf < 4; mf++) {
                int row = mw*64 + mf*16 + (lane & 15);
                int col = ks*16 + (lane >> 4) * 8;
                uint32_t off = sw64((uint32_t)(row * 64 + col * 2));
                ldsm4s(afh[mf], sb + off);
                ldsm4s(afl[mf], sb + 8192 + off);
            }
#pragma unroll
            for (int nf = 0; nf < 4; nf++) {
                int li = lane & 15;
                int row = nw*32 + nf*8 + (li & 7);
                int col = ks*16 + (li >> 3) * 8;
                uint32_t off = sw64((uint32_t)(row * 64 + col * 2));
                ldsm2s(bfh[nf], sb + 16384 + off);
                ldsm2s(bfl[nf], sb + 24576 + off);
            }
            // term-ordered: reuse distance per accumulator = 16 MMAs
#pragma unroll
            for (int mf = 0; mf < 4; mf++)
#pragma unroll
                for (int nf = 0; nf < 4; nf++)
                    mma16816(acc[mf][nf], afh[mf], bfh[nf]);
#pragma unroll
            for (int mf = 0; mf < 4; mf++)
#pragma unroll
                for (int nf = 0; nf < 4; nf++)
                    mma16816(acc[mf][nf], afh[mf], bfl[nf]);
#pragma unroll
            for (int mf = 0; mf < 4; mf++)
#pragma unroll
                for (int nf = 0; nf < 4; nf++)
                    mma16816(acc[mf][nf], afl[mf], bfh[nf]);
        }
    }

#pragma unroll
    for (int mf = 0; mf < 4; mf++)
#pragma unroll
        for (int nf = 0; nf < 4; nf++)
#pragma unroll
            for (int c = 0; c < 2; c++) {
                int row = bm + mw*64 + mf*16 + (lane >> 2) + c*8;
                int col = bn + nw*32 + nf*8  + 2*(lane & 3);
                float v0 = acc[mf][nf][2*c+0];
                float v1 = acc[mf][nf][2*c+1];
                if (bias) { v0 += bias[col]; v1 += bias[col+1]; }
                if (Cf) *(float2*)&Cf[(size_t)row * N + col] = make_float2(v0, v1);
                if (Ch) {
                    uint32_t ph, pl;
                    split_pack2(v0, v1, ph, pl);
                    *(uint32_t*)&Ch[(size_t)row * N + col] = ph;
                    *(uint32_t*)&Cl[(size_t)row * N + col] = pl;
                }
            }
}

// ---------------- one-pass attention, 2 CTAs/SM ----------------
// grid (SEQ/128, B*H), 256 threads = 8 warps, each warp owns 16 query rows.
// MMA groups interleave the two accumulators (reuse distance 2).
#define KBUF 4608   // 64*72 elements per K/V buffer
__global__ __launch_bounds__(256, 2)
void attn_one(const bf16* __restrict__ qh, const bf16* __restrict__ ql,
              const int* __restrict__ mask,
              float* __restrict__ attn,
              bf16* __restrict__ ctxh, bf16* __restrict__ ctxl)
{
    char* sm = dynsm;
    bf16*  sQh  = (bf16*)sm;                    // 128*72
    bf16*  sQl  = (bf16*)(sm + 18432);
    bf16*  sKb  = (bf16*)(sm + 36864);          // [2 st][2 hl][64*72]
    bf16*  sVb  = (bf16*)(sm + 73728);
    int*   smask = (int*)(sm + 110592);         // [2][64]
    float* lrec  = (float*)(sm + 111104);       // [128]

    const int tid = threadIdx.x, lane = tid & 31, w = tid >> 5;
    const int q0 = blockIdx.x * QT;
    const int bh = blockIdx.y, b = bh >> 4, h = bh & 15;
    const size_t RS = 3 * DMODEL;

    for (int s = tid; s < 1024; s += 256) {
        int r = s >> 3, c = (s & 7) * 8;
        size_t g = (size_t)(b*SEQ + q0 + r) * RS + h*DHEAD + c;
        cpa16(&sQh[r*72 + c], qh + g);
        cpa16(&sQl[r*72 + c], ql + g);
    }
    cpcommit();

    auto stageKV = [&](int st, int kt) {
        int k0 = kt * 64;
        if (tid < 64) smask[st*64 + tid] = mask[b*SEQ + k0 + tid];
        for (int s = tid; s < 512; s += 256) {
            int r = s >> 3, c = (s & 7) * 8;
            size_t gk = (size_t)(b*SEQ + k0 + r) * RS + DMODEL + h*DHEAD + c;
            size_t gv = gk + DMODEL;
            cpa16(&sKb[(st*2+0)*KBUF + r*72 + c], qh + gk);
            cpa16(&sKb[(st*2+1)*KBUF + r*72 + c], ql + gk);
            cpa16(&sVb[(st*2+0)*KBUF + r*72 + c], qh + gv);
            cpa16(&sVb[(st*2+1)*KBUF + r*72 + c], ql + gv);
        }
        cpcommit();
    };

    stageKV(0, 0);
    cpwait0();
    __syncthreads();

    float oacc[8][4];
#pragma unroll
    for (int nf = 0; nf < 8; nf++)
#pragma unroll
        for (int c = 0; c < 4; c++) oacc[nf][c] = 0.f;
    float rs0 = 0.f, rs1 = 0.f;

    const int rlo = lane >> 2, qq = lane & 3;
    const int g8 = lane >> 3;
    const size_t abase = ((size_t)bh * SEQ + q0) * SEQ;

    for (int kt = 0; kt < 16; kt++) {
        int st = kt & 1;
        if (kt) { cpwait0(); __syncthreads(); }
        if (kt + 1 < 16) stageKV(st ^ 1, kt + 1);

        float sacc[8][4];
#pragma unroll
        for (int nf = 0; nf < 8; nf++)
#pragma unroll
            for (int c = 0; c < 4; c++) sacc[nf][c] = 0.f;

#pragma unroll
        for (int ks = 0; ks < 4; ks++) {
            uint32_t q4h[4], q4l[4];
            int qoff = (w*16 + (lane & 15)) * 72 + ks*16 + (lane >> 4) * 8;
            ldsm4(q4h, &sQh[qoff]);
            ldsm4(q4l, &sQl[qoff]);
#pragma unroll
            for (int p = 0; p < 4; p++) {
                int off = (p*16 + (g8 & 1)*8 + (lane & 7)) * 72 + ks*16 + (g8 >> 1) * 8;
                uint32_t r4[4], s4[4];
                ldsm4(r4, &sKb[(st*2+0)*KBUF + off]);
                ldsm4(s4, &sKb[(st*2+1)*KBUF + off]);
                uint32_t b0[2] = {r4[0], r4[2]}, b1[2] = {r4[1], r4[3]};
                uint32_t c0[2] = {s4[0], s4[2]}, c1[2] = {s4[1], s4[3]};
                // interleave the two accumulators (distance 2)
                mma16816(sacc[2*p],   q4h, b0);
                mma16816(sacc[2*p+1], q4h, b1);
                mma16816(sacc[2*p],   q4h, c0);
                mma16816(sacc[2*p+1], q4h, c1);
                mma16816(sacc[2*p],   q4l, b0);
                mma16816(sacc[2*p+1], q4l, b1);
            }
        }

#pragma unroll
        for (int nf = 0; nf < 8; nf++) {
            int c0i = nf*8 + 2*qq;
            int m0 = smask[st*64 + c0i];
            int m1 = smask[st*64 + c0i + 1];
            float e0 = m0 ? fexp2p(sacc[nf][0] * Y_SCALE) : 0.f;
            float e1 = m1 ? fexp2p(sacc[nf][1] * Y_SCALE) : 0.f;
            float e2 = m0 ? fexp2p(sacc[nf][2] * Y_SCALE) : 0.f;
            float e3 = m1 ? fexp2p(sacc[nf][3] * Y_SCALE) : 0.f;
            sacc[nf][0] = e0; sacc[nf][1] = e1; sacc[nf][2] = e2; sacc[nf][3] = e3;
            rs0 += e0 + e1;
            rs1 += e2 + e3;
            size_t a0 = abase + (size_t)(w*16 + rlo) * SEQ + kt*64 + c0i;
            *(float2*)&attn[a0]           = make_float2(e0, e1);
            *(float2*)&attn[a0 + 8*SEQ]   = make_float2(e2, e3);
        }

#pragma unroll
        for (int pk = 0; pk < 4; pk++) {
            uint32_t ah[4], al[4];
            split_pack2(sacc[2*pk][0],   sacc[2*pk][1],   ah[0], al[0]);
            split_pack2(sacc[2*pk][2],   sacc[2*pk][3],   ah[1], al[1]);
            split_pack2(sacc[2*pk+1][0], sacc[2*pk+1][1], ah[2], al[2]);
            split_pack2(sacc[2*pk+1][2], sacc[2*pk+1][3], ah[3], al[3]);
#pragma unroll
            for (int p = 0; p < 4; p++) {
                int off = (pk*16 + (g8 & 1)*8 + (lane & 7)) * 72 + (2*p + (g8 >> 1)) * 8;
                uint32_t r4[4], s4[4];
                ldsm4t(r4, &sVb[(st*2+0)*KBUF + off]);
                ldsm4t(s4, &sVb[(st*2+1)*KBUF + off]);
                uint32_t v0[2] = {r4[0], r4[1]}, v1[2] = {r4[2], r4[3]};
                uint32_t u0[2] = {s4[0], s4[1]}, u1[2] = {s4[2], s4[3]};
                // interleave the two accumulators (distance 2)
                mma16816(oacc[2*p],   ah, v0);
                mma16816(oacc[2*p+1], ah, v1);
                mma16816(oacc[2*p],   ah, u0);
                mma16816(oacc[2*p+1], ah, u1);
                mma16816(oacc[2*p],   al, v0);
                mma16816(oacc[2*p+1], al, v1);
            }
        }
    }

    rs0 += __shfl_xor_sync(0xffffffffu, rs0, 1);
    rs0 += __shfl_xor_sync(0xffffffffu, rs0, 2);
    rs1 += __shfl_xor_sync(0xffffffffu, rs1, 1);
    rs1 += __shfl_xor_sync(0xffffffffu, rs1, 2);
    float ri0 = 1.f / rs0, ri1 = 1.f / rs1;
    if ((lane & 3) == 0) {
        lrec[w*16 + rlo]     = ri0;
        lrec[w*16 + rlo + 8] = ri1;
    }

    const size_t row0 = (size_t)(b*SEQ + q0 + w*16 + rlo);
#pragma unroll
    for (int nf = 0; nf < 8; nf++) {
        int col = h*DHEAD + nf*8 + 2*qq;
        uint32_t hp, lp;
        split_pack2(oacc[nf][0] * ri0, oacc[nf][1] * ri0, hp, lp);
        *(uint32_t*)&ctxh[row0*DMODEL + col] = hp;
        *(uint32_t*)&ctxl[row0*DMODEL + col] = lp;
        split_pack2(oacc[nf][2] * ri1, oacc[nf][3] * ri1, hp, lp);
        *(uint32_t*)&ctxh[(row0+8)*DMODEL + col] = hp;
        *(uint32_t*)&ctxl[(row0+8)*DMODEL + col] = lp;
    }

    __syncthreads();

    for (int s = tid; s < QT * 256; s += 256) {
        int r = s >> 8, c = (s & 255) * 4;
        float sc = lrec[r];
        float4* p = (float4*)(attn + abase + (size_t)r * SEQ + c);
        float4 v = *p;
        v.x *= sc; v.y *= sc; v.z *= sc; v.w *= sc;
        *p = v;
    }
}

// ---------------- launcher ----------------
extern "C" void kernel_launch(void* const* d_in, const int* in_sizes, int n_in,
                              void* d_out, int out_size)
{
    const float* x     = (const float*)d_in[0];
    const int*   mask  = (const int*)d_in[1];
    const float* w_qkv = (const float*)d_in[2];
    const float* w_out = (const float*)d_in[3];
    const float* b_out = (const float*)d_in[4];

    float* out  = (float*)d_out;
    float* attn = out + MROWS * DMODEL;

    bf16 *xh, *xl, *wqh, *wql, *woh, *wol, *qkvh, *qkvl, *ctxh, *ctxl;
    cudaGetSymbolAddress((void**)&xh,  g_xh);  cudaGetSymbolAddress((void**)&xl,  g_xl);
    cudaGetSymbolAddress((void**)&wqh, g_wqt_h); cudaGetSymbolAddress((void**)&wql, g_wqt_l);
    cudaGetSymbolAddress((void**)&woh, g_wot_h); cudaGetSymbolAddress((void**)&wol, g_wot_l);
    cudaGetSymbolAddress((void**)&qkvh, g_qkvh); cudaGetSymbolAddress((void**)&qkvl, g_qkvl);
    cudaGetSymbolAddress((void**)&ctxh, g_ctxh); cudaGetSymbolAddress((void**)&ctxl, g_ctxl);

    cudaFuncSetAttribute(mma_gemm, cudaFuncAttributeMaxDynamicSharedMemorySize, 99328);
    cudaFuncSetAttribute(attn_one, cudaFuncAttributeMaxDynamicSharedMemorySize, 111616);

    {
        int n4 = (int)(MROWS * DMODEL / 4);
        split_kernel<<<(n4 + 255) / 256, 256>>>(x, xh, xl, n4);
    }
    transpose_split<<<dim3(3*DMODEL/32, DMODEL/32), dim3(32,8)>>>(w_qkv, wqh, wql, DMODEL, 3*DMODEL);
    transpose_split<<<dim3(DMODEL/32,   DMODEL/32), dim3(32,8)>>>(w_out, woh, wol, DMODEL, DMODEL);

    mma_gemm<<<dim3(3*DMODEL/128, (int)(MROWS/128)), 256, 99328>>>(
        xh, xl, wqh, wql, nullptr, qkvh, qkvl, nullptr,
        (int)MROWS, 3*DMODEL, DMODEL);

    attn_one<<<dim3(SEQ/QT, BDIM*NHEAD), 256, 111616>>>(
        qkvh, qkvl, mask, attn, ctxh, ctxl);

    mma_gemm<<<dim3(DMODEL/128, (int)(MROWS/128)), 256, 99328>>>(
        ctxh, ctxl, woh, wol, out, nullptr, nullptr, b_out,
        (int)MROWS, DMODEL, DMODEL);
}